// round 9
// baseline (speedup 1.0000x reference)
#include <cuda_runtime.h>
#include <cstdint>

#define DIMK 1024
#define BSZ  2
#define SEQ  4096
#define H    16
#define HD   64
#define M_TOT (BSZ * SEQ)   // 8192

// ---------------------------------------------------------------------------
// Scratch (allocation-free)
// ---------------------------------------------------------------------------
__device__ float g_q[(size_t)BSZ * H * SEQ * HD];
__device__ float g_k[(size_t)BSZ * H * SEQ * HD];
__device__ float g_v[(size_t)BSZ * H * SEQ * HD];
__device__ float g_att[(size_t)BSZ * SEQ * DIMK];

__device__ __forceinline__ uint32_t f32_tf32(float f) {
    uint32_t r; asm("cvt.rna.tf32.f32 %0, %1;" : "=r"(r) : "f"(f)); return r;
}
__device__ __forceinline__ float ex2f(float x) {
    float r; asm("ex2.approx.f32 %0, %1;" : "=f"(r) : "f"(x)); return r;
}

__device__ __forceinline__ void mma_tf32(float& c0, float& c1, float& c2, float& c3,
                                         uint32_t a0, uint32_t a1, uint32_t a2, uint32_t a3,
                                         uint32_t b0, uint32_t b1) {
    asm volatile("mma.sync.aligned.m16n8k8.row.col.f32.tf32.tf32.f32 "
        "{%0,%1,%2,%3}, {%4,%5,%6,%7}, {%8,%9}, {%0,%1,%2,%3};"
        : "+f"(c0), "+f"(c1), "+f"(c2), "+f"(c3)
        : "r"(a0), "r"(a1), "r"(a2), "r"(a3), "r"(b0), "r"(b1));
}

// ---------------------------------------------------------------------------
// tf32 mma.sync GEMM, double-buffered smem, 1 barrier/chunk, prefetch.
// C = A @ W^T + bias. CTA 128x128, BK=32, 8 warps (2M x 4N), warp 64x32.
// blockIdx.z selects (W, bias, C) — fuses the QKV projections.
// layout 0: row-major [M,1024] ; layout 1: scatter to [B,H,S,hd]
// ---------------------------------------------------------------------------
#define BM 128
#define BN 128
#define BK 32
#define KST 36
#define SM_GEMM (2 * (BM + BN) * KST * 4)   // 73728 B

__global__ void __launch_bounds__(256) gemm_mma(const float* __restrict__ A,
                                                const float* __restrict__ W0,
                                                const float* __restrict__ W1,
                                                const float* __restrict__ W2,
                                                const float* __restrict__ b0p,
                                                const float* __restrict__ b1p,
                                                const float* __restrict__ b2p,
                                                float* __restrict__ C0,
                                                float* __restrict__ C1,
                                                float* __restrict__ C2,
                                                int layout)
{
    extern __shared__ __align__(16) uint32_t gsm[];

    const int z = blockIdx.z;
    const float* W    = (z == 0) ? W0 : (z == 1) ? W1 : W2;
    const float* bias = (z == 0) ? b0p : (z == 1) ? b1p : b2p;
    float*       C    = (z == 0) ? C0 : (z == 1) ? C1 : C2;

    const int tid  = threadIdx.x;
    const int wid  = tid >> 5;
    const int lane = tid & 31;
    const int g    = lane >> 2;
    const int t    = lane & 3;
    const int wm   = wid & 1;
    const int wn   = wid >> 1;
    const int m0   = blockIdx.y * BM;
    const int n0   = blockIdx.x * BN;

    const int lrow = tid >> 3;        // 0..31
    const int lc4  = (tid & 7) << 2;  // 0..28 step 4

    float acc[4][4][4];
#pragma unroll
    for (int i = 0; i < 4; i++)
#pragma unroll
        for (int j = 0; j < 4; j++)
#pragma unroll
            for (int r = 0; r < 4; r++) acc[i][j][r] = 0.f;

    const int warpAm = wm * 64;
    const int warpBn = wn * 32;

    // prologue: prefetch chunk 0
    float4 av[4], wv[4];
#pragma unroll
    for (int it = 0; it < 4; it++) {
        const int row = lrow + (it << 5);
        av[it] = *(const float4*)(A + (size_t)(m0 + row) * DIMK + lc4);
        wv[it] = *(const float4*)(W + (size_t)(n0 + row) * DIMK + lc4);
    }

#pragma unroll 2
    for (int c = 0; c < 32; c++) {
        uint32_t* As = gsm + (c & 1) * ((BM + BN) * KST);
        uint32_t* Bs = As + BM * KST;

        // store current chunk (cvt to tf32)
#pragma unroll
        for (int it = 0; it < 4; it++) {
            const int row = lrow + (it << 5);
            uint4 ta, tw;
            ta.x = f32_tf32(av[it].x); ta.y = f32_tf32(av[it].y);
            ta.z = f32_tf32(av[it].z); ta.w = f32_tf32(av[it].w);
            tw.x = f32_tf32(wv[it].x); tw.y = f32_tf32(wv[it].y);
            tw.z = f32_tf32(wv[it].z); tw.w = f32_tf32(wv[it].w);
            *(uint4*)&As[row * KST + lc4] = ta;
            *(uint4*)&Bs[row * KST + lc4] = tw;
        }
        // prefetch next chunk (hidden under this chunk's MMA)
        if (c < 31) {
            const int k0 = (c + 1) * BK;
#pragma unroll
            for (int it = 0; it < 4; it++) {
                const int row = lrow + (it << 5);
                av[it] = *(const float4*)(A + (size_t)(m0 + row) * DIMK + k0 + lc4);
                wv[it] = *(const float4*)(W + (size_t)(n0 + row) * DIMK + k0 + lc4);
            }
        }
        __syncthreads();   // single barrier: CTA fence orders LDS(c-2) < STS(c)

#pragma unroll
        for (int ks = 0; ks < 4; ks++) {
            const int kk = ks << 3;
            uint32_t af[4][4], bf[4][2];
#pragma unroll
            for (int mt = 0; mt < 4; mt++) {
                const int rb = warpAm + (mt << 4);
                af[mt][0] = As[(rb + g    ) * KST + kk + t    ];
                af[mt][1] = As[(rb + g + 8) * KST + kk + t    ];
                af[mt][2] = As[(rb + g    ) * KST + kk + t + 4];
                af[mt][3] = As[(rb + g + 8) * KST + kk + t + 4];
            }
#pragma unroll
            for (int nt = 0; nt < 4; nt++) {
                const int nb = warpBn + (nt << 3);
                bf[nt][0] = Bs[(nb + g) * KST + kk + t    ];
                bf[nt][1] = Bs[(nb + g) * KST + kk + t + 4];
            }
#pragma unroll
            for (int mt = 0; mt < 4; mt++)
#pragma unroll
                for (int nt = 0; nt < 4; nt++)
                    mma_tf32(acc[mt][nt][0], acc[mt][nt][1],
                             acc[mt][nt][2], acc[mt][nt][3],
                             af[mt][0], af[mt][1], af[mt][2], af[mt][3],
                             bf[nt][0], bf[nt][1]);
        }
    }

#pragma unroll
    for (int nt = 0; nt < 4; nt++) {
        const int n = n0 + warpBn + (nt << 3) + (t << 1);
        const float bx = bias[n], by = bias[n + 1];
#pragma unroll
        for (int mt = 0; mt < 4; mt++) {
            const int r0 = m0 + warpAm + (mt << 4) + g;
            const int r1 = r0 + 8;
            float2 v0 = make_float2(acc[mt][nt][0] + bx, acc[mt][nt][1] + by);
            float2 v1 = make_float2(acc[mt][nt][2] + bx, acc[mt][nt][3] + by);
            if (layout == 0) {
                *(float2*)(C + (size_t)r0 * DIMK + n) = v0;
                *(float2*)(C + (size_t)r1 * DIMK + n) = v1;
            } else {
                const int h_ = n >> 6, d_ = n & 63;
                const int b0_ = r0 >> 12, s0_ = r0 & 4095;
                const int b1_ = r1 >> 12, s1_ = r1 & 4095;
                *(float2*)(C + (((size_t)(b0_ * H + h_)) * SEQ + s0_) * HD + d_) = v0;
                *(float2*)(C + (((size_t)(b1_ * H + h_)) * SEQ + s1_) * HD + d_) = v1;
            }
        }
    }
}

// ---------------------------------------------------------------------------
// Tensorized sliding-window attention.
// CTA = (b, h, 64-query tile), 128 threads / 4 warps, warp owns 16 rows.
// Ps aliases Ks (smem 52 KB -> 4 CTAs/SM); V in stride-72 array so the
// transposed PV B-fragment read is bank-conflict-free.
// ---------------------------------------------------------------------------
#define AST 68
#define VST 72
#define SMEM_AMMA ((2 * 64 * AST + 64 * VST) * 4)   // 53248 B

__global__ void __launch_bounds__(128) attn_mma()
{
    extern __shared__ __align__(16) uint32_t smu[];
    uint32_t* Qs = smu;                  // [64][AST] tf32
    uint32_t* Ks = smu + 64 * AST;       // [64][AST] tf32 ; reused as Ps
    uint32_t* Vs = smu + 2 * 64 * AST;   // [64][VST] tf32

    const int tid  = threadIdx.x;
    const int w    = tid >> 5;
    const int lane = tid & 31;
    const int g    = lane >> 2;
    const int t    = lane & 3;

    const int qi = blockIdx.x & 63;
    const int h  = (blockIdx.x >> 6) & 15;
    const int b  = blockIdx.x >> 10;
    const int p0 = qi << 6;

    const size_t headoff = ((size_t)(b * H + h)) * SEQ * HD;
    const float* qbase = g_q + headoff;
    const float* kbase = g_k + headoff;
    const float* vbase = g_v + headoff;

    // stage Q (tf32)
#pragma unroll
    for (int it = 0; it < 8; it++) {
        const int u = tid + (it << 7);
        const int row = u >> 4, c4 = (u & 15) << 2;
        float4 v = *(const float4*)(qbase + (size_t)(p0 + row) * HD + c4);
        uint4 tv;
        tv.x = f32_tf32(v.x); tv.y = f32_tf32(v.y);
        tv.z = f32_tf32(v.z); tv.w = f32_tf32(v.w);
        *(uint4*)&Qs[row * AST + c4] = tv;
    }
    __syncthreads();

    const int r0 = (w << 4) + g;
    const int q0 = p0 + r0;
    const int q1 = q0 + 8;

    float O[8][4];
#pragma unroll
    for (int nt = 0; nt < 8; nt++)
#pragma unroll
        for (int r = 0; r < 4; r++) O[nt][r] = 0.f;
    float m0 = -1.0e4f, m1 = -1.0e4f, l0 = 0.f, l1 = 0.f;

    const float SC = 0.125f * 1.44269504f;   // hd^-0.5 * log2(e)

    const int ktlo = (qi >= 8) ? (qi - 8) : 0;
    for (int kt = ktlo; kt <= qi; kt++) {
        const int t0 = kt << 6;

        __syncthreads();   // prior PV reads of Ps/Vs complete
#pragma unroll
        for (int it = 0; it < 8; it++) {
            const int u = tid + (it << 7);
            const int row = u >> 4, c4 = (u & 15) << 2;
            float4 kv = *(const float4*)(kbase + (size_t)(t0 + row) * HD + c4);
            float4 vv = *(const float4*)(vbase + (size_t)(t0 + row) * HD + c4);
            uint4 tk, tv;
            tk.x = f32_tf32(kv.x); tk.y = f32_tf32(kv.y);
            tk.z = f32_tf32(kv.z); tk.w = f32_tf32(kv.w);
            tv.x = f32_tf32(vv.x); tv.y = f32_tf32(vv.y);
            tv.z = f32_tf32(vv.z); tv.w = f32_tf32(vv.w);
            *(uint4*)&Ks[row * AST + c4] = tk;
            *(uint4*)&Vs[row * VST + c4] = tv;
        }
        __syncthreads();

        // S = Q K^T
        float s[8][4];
#pragma unroll
        for (int nt = 0; nt < 8; nt++)
#pragma unroll
            for (int r = 0; r < 4; r++) s[nt][r] = 0.f;

#pragma unroll
        for (int ks = 0; ks < 8; ks++) {
            const int kk = ks << 3;
            const uint32_t a0 = Qs[r0 * AST + kk + t];
            const uint32_t a1 = Qs[(r0 + 8) * AST + kk + t];
            const uint32_t a2 = Qs[r0 * AST + kk + t + 4];
            const uint32_t a3 = Qs[(r0 + 8) * AST + kk + t + 4];
#pragma unroll
            for (int nt = 0; nt < 8; nt++) {
                const uint32_t b0 = Ks[((nt << 3) + g) * AST + kk + t];
                const uint32_t b1 = Ks[((nt << 3) + g) * AST + kk + t + 4];
                mma_tf32(s[nt][0], s[nt][1], s[nt][2], s[nt][3],
                         a0, a1, a2, a3, b0, b1);
            }
        }

        // mask + scale (log2 domain) + online softmax
        float rmax0 = -3.0e4f, rmax1 = -3.0e4f;
#pragma unroll
        for (int nt = 0; nt < 8; nt++) {
            const int c = t0 + (nt << 3) + (t << 1);
            s[nt][0] = ((unsigned)(q0 - c)     < 512u) ? s[nt][0] * SC : -3.0e4f;
            s[nt][1] = ((unsigned)(q0 - c - 1) < 512u) ? s[nt][1] * SC : -3.0e4f;
            s[nt][2] = ((unsigned)(q1 - c)     < 512u) ? s[nt][2] * SC : -3.0e4f;
            s[nt][3] = ((unsigned)(q1 - c - 1) < 512u) ? s[nt][3] * SC : -3.0e4f;
            rmax0 = fmaxf(rmax0, fmaxf(s[nt][0], s[nt][1]));
            rmax1 = fmaxf(rmax1, fmaxf(s[nt][2], s[nt][3]));
        }
        rmax0 = fmaxf(rmax0, __shfl_xor_sync(0xffffffffu, rmax0, 1));
        rmax0 = fmaxf(rmax0, __shfl_xor_sync(0xffffffffu, rmax0, 2));
        rmax1 = fmaxf(rmax1, __shfl_xor_sync(0xffffffffu, rmax1, 1));
        rmax1 = fmaxf(rmax1, __shfl_xor_sync(0xffffffffu, rmax1, 2));

        const float mn0 = fmaxf(m0, rmax0);
        const float mn1 = fmaxf(m1, rmax1);
        const float al0 = ex2f(m0 - mn0);
        const float al1 = ex2f(m1 - mn1);
        m0 = mn0; m1 = mn1;

        float rs0 = 0.f, rs1 = 0.f;
        uint2 pw0[8], pw1[8];
#pragma unroll
        for (int nt = 0; nt < 8; nt++) {
            const float p00 = ex2f(s[nt][0] - mn0);
            const float p01 = ex2f(s[nt][1] - mn0);
            const float p10 = ex2f(s[nt][2] - mn1);
            const float p11 = ex2f(s[nt][3] - mn1);
            rs0 += p00 + p01;
            rs1 += p10 + p11;
            pw0[nt] = make_uint2(f32_tf32(p00), f32_tf32(p01));
            pw1[nt] = make_uint2(f32_tf32(p10), f32_tf32(p11));
        }
        rs0 += __shfl_xor_sync(0xffffffffu, rs0, 1);
        rs0 += __shfl_xor_sync(0xffffffffu, rs0, 2);
        rs1 += __shfl_xor_sync(0xffffffffu, rs1, 1);
        rs1 += __shfl_xor_sync(0xffffffffu, rs1, 2);

        l0 = l0 * al0 + rs0;
        l1 = l1 * al1 + rs1;
#pragma unroll
        for (int nt = 0; nt < 8; nt++) {
            O[nt][0] *= al0; O[nt][1] *= al0;
            O[nt][2] *= al1; O[nt][3] *= al1;
        }

        __syncthreads();   // all warps' K-fragment reads done -> safe to alias
        uint32_t* Ps = Ks;
#pragma unroll
        for (int nt = 0; nt < 8; nt++) {
            const int cc = (nt << 3) + (t << 1);
            *(uint2*)&Ps[r0 * AST + cc]       = pw0[nt];
            *(uint2*)&Ps[(r0 + 8) * AST + cc] = pw1[nt];
        }
        __syncwarp();      // Ps rows are warp-private

        // O += P V   (V read transposed, stride 72 => conflict-free)
#pragma unroll
        for (int ks = 0; ks < 8; ks++) {
            const int kk = ks << 3;
            const uint32_t a0 = Ps[r0 * AST + kk + t];
            const uint32_t a1 = Ps[(r0 + 8) * AST + kk + t];
            const uint32_t a2 = Ps[r0 * AST + kk + t + 4];
            const uint32_t a3 = Ps[(r0 + 8) * AST + kk + t + 4];
#pragma unroll
            for (int nt = 0; nt < 8; nt++) {
                const uint32_t b0 = Vs[(kk + t) * VST + (nt << 3) + g];
                const uint32_t b1 = Vs[(kk + t + 4) * VST + (nt << 3) + g];
                mma_tf32(O[nt][0], O[nt][1], O[nt][2], O[nt][3],
                         a0, a1, a2, a3, b0, b1);
            }
        }
    }

    // epilogue
    const float inv0 = 1.f / l0;
    const float inv1 = 1.f / l1;
    float* dst0 = g_att + ((size_t)b * SEQ + q0) * DIMK + h * HD;
    float* dst1 = g_att + ((size_t)b * SEQ + q1) * DIMK + h * HD;
#pragma unroll
    for (int nt = 0; nt < 8; nt++) {
        const int cc = (nt << 3) + (t << 1);
        *(float2*)(dst0 + cc) = make_float2(O[nt][0] * inv0, O[nt][1] * inv0);
        *(float2*)(dst1 + cc) = make_float2(O[nt][2] * inv1, O[nt][3] * inv1);
    }
}

// ---------------------------------------------------------------------------
extern "C" void kernel_launch(void* const* d_in, const int* in_sizes, int n_in,
                              void* d_out, int out_size)
{
    const float* x  = (const float*)d_in[0];
    const float* Wq = (const float*)d_in[1];
    const float* bq = (const float*)d_in[2];
    const float* Wk = (const float*)d_in[3];
    const float* bk = (const float*)d_in[4];
    const float* Wv = (const float*)d_in[5];
    const float* bv = (const float*)d_in[6];
    const float* Wo = (const float*)d_in[7];
    const float* bo = (const float*)d_in[8];
    float* out = (float*)d_out;

    float *qp, *kp, *vp, *ap;
    cudaGetSymbolAddress((void**)&qp, g_q);
    cudaGetSymbolAddress((void**)&kp, g_k);
    cudaGetSymbolAddress((void**)&vp, g_v);
    cudaGetSymbolAddress((void**)&ap, g_att);

    cudaFuncSetAttribute(gemm_mma,
                         cudaFuncAttributeMaxDynamicSharedMemorySize, SM_GEMM);
    cudaFuncSetAttribute(attn_mma,
                         cudaFuncAttributeMaxDynamicSharedMemorySize, SMEM_AMMA);

    dim3 gqkv(DIMK / BN, M_TOT / BM, 3);   // fused Q/K/V projections
    gemm_mma<<<gqkv, 256, SM_GEMM>>>(x, Wq, Wk, Wv, bq, bk, bv, qp, kp, vp, 1);
    attn_mma<<<BSZ * H * (SEQ / 64), 128, SMEM_AMMA>>>();
    dim3 go(DIMK / BN, M_TOT / BM, 1);     // output projection
    gemm_mma<<<go, 256, SM_GEMM>>>(ap, Wo, Wo, Wo, bo, bo, bo, out, out, out, 0);
}

// round 10
// speedup vs baseline: 1.1903x; 1.1903x over previous
#include <cuda_runtime.h>
#include <cstdint>

#define DIMK 1024
#define BSZ  2
#define SEQ  4096
#define H    16
#define HD   64
#define M_TOT (BSZ * SEQ)   // 8192

// ---------------------------------------------------------------------------
// Scratch (allocation-free). All tf32 bit patterns stored as u32.
// ---------------------------------------------------------------------------
__device__ uint32_t g_q[(size_t)BSZ * H * SEQ * HD];
__device__ uint32_t g_k[(size_t)BSZ * H * SEQ * HD];
__device__ uint32_t g_v[(size_t)BSZ * H * SEQ * HD];
__device__ uint32_t g_att[(size_t)BSZ * SEQ * DIMK];
__device__ uint32_t g_x32[(size_t)M_TOT * DIMK];
__device__ uint32_t g_w32[4][(size_t)DIMK * DIMK];

__device__ __forceinline__ uint32_t f32_tf32(float f) {
    uint32_t r; asm("cvt.rna.tf32.f32 %0, %1;" : "=r"(r) : "f"(f)); return r;
}
__device__ __forceinline__ float ex2f(float x) {
    float r; asm("ex2.approx.f32 %0, %1;" : "=f"(r) : "f"(x)); return r;
}
__device__ __forceinline__ uint32_t smem_u32(const void* p) {
    uint32_t a;
    asm("{ .reg .u64 t; cvta.to.shared.u64 t, %1; cvt.u32.u64 %0, t; }" : "=r"(a) : "l"(p));
    return a;
}
__device__ __forceinline__ void cp16(uint32_t s, const void* g) {
    asm volatile("cp.async.cg.shared.global [%0], [%1], 16;" :: "r"(s), "l"(g));
}
#define CP_COMMIT()  asm volatile("cp.async.commit_group;" ::: "memory")
#define CP_WAIT(n)   asm volatile("cp.async.wait_group %0;" :: "n"(n) : "memory")

__device__ __forceinline__ void mma_tf32(float& c0, float& c1, float& c2, float& c3,
                                         uint32_t a0, uint32_t a1, uint32_t a2, uint32_t a3,
                                         uint32_t b0, uint32_t b1) {
    asm volatile("mma.sync.aligned.m16n8k8.row.col.f32.tf32.tf32.f32 "
        "{%0,%1,%2,%3}, {%4,%5,%6,%7}, {%8,%9}, {%0,%1,%2,%3};"
        : "+f"(c0), "+f"(c1), "+f"(c2), "+f"(c3)
        : "r"(a0), "r"(a1), "r"(a2), "r"(a3), "r"(b0), "r"(b1));
}

// ---------------------------------------------------------------------------
// fp32 -> tf32 bit-pattern conversion pass (vectorized)
// ---------------------------------------------------------------------------
__global__ void __launch_bounds__(256) conv_tf32(const float* __restrict__ src,
                                                 uint32_t* __restrict__ dst, int n4)
{
    const int i = blockIdx.x * blockDim.x + threadIdx.x;
    if (i < n4) {
        float4 v = ((const float4*)src)[i];
        uint4 t;
        t.x = f32_tf32(v.x); t.y = f32_tf32(v.y);
        t.z = f32_tf32(v.z); t.w = f32_tf32(v.w);
        ((uint4*)dst)[i] = t;
    }
}

// ---------------------------------------------------------------------------
// tf32 mma.sync GEMM, 3-stage cp.async pipeline, 1 barrier/chunk, no cvt.
// A, W pre-converted tf32 u32. CTA 128x128, BK=32, 8 warps (2M x 4N).
// layout 1: scatter tf32 u32 -> [B,H,S,hd] (z = 0,1,2 for Q,K,V)
// layout 0: fp32 row-major [M,1024]
// ---------------------------------------------------------------------------
#define BM 128
#define BN 128
#define BK 32
#define KST 36
#define STGW ((BM + BN) * KST)          // words per stage (9216)
#define SM_GEMM (3 * STGW * 4)          // 110592 B

__global__ void __launch_bounds__(256, 2) gemm_mma(const uint32_t* __restrict__ A,
                                                   const uint32_t* __restrict__ W0,
                                                   const uint32_t* __restrict__ W1,
                                                   const uint32_t* __restrict__ W2,
                                                   const float* __restrict__ b0p,
                                                   const float* __restrict__ b1p,
                                                   const float* __restrict__ b2p,
                                                   uint32_t* __restrict__ C0,
                                                   uint32_t* __restrict__ C1,
                                                   uint32_t* __restrict__ C2,
                                                   float* __restrict__ Cf,
                                                   int layout)
{
    extern __shared__ __align__(16) uint32_t gsm[];

    const int z = blockIdx.z;
    const uint32_t* W    = (z == 0) ? W0 : (z == 1) ? W1 : W2;
    const float*    bias = (z == 0) ? b0p : (z == 1) ? b1p : b2p;
    uint32_t*       C    = (z == 0) ? C0 : (z == 1) ? C1 : C2;

    const int tid  = threadIdx.x;
    const int wid  = tid >> 5;
    const int lane = tid & 31;
    const int g    = lane >> 2;
    const int t    = lane & 3;
    const int wm   = wid & 1;
    const int wn   = wid >> 1;
    const int m0   = blockIdx.y * BM;
    const int n0   = blockIdx.x * BN;

    const int lrow = tid >> 3;        // 0..31
    const int lc4  = (tid & 7) << 2;  // 0..28 step 4

    const uint32_t smb = smem_u32(gsm);

    float acc[4][4][4];
#pragma unroll
    for (int i = 0; i < 4; i++)
#pragma unroll
        for (int j = 0; j < 4; j++)
#pragma unroll
            for (int r = 0; r < 4; r++) acc[i][j][r] = 0.f;

    const int warpAm = wm * 64;
    const int warpBn = wn * 32;

    const uint32_t* Abase = A + (size_t)(m0 + lrow) * DIMK + lc4;
    const uint32_t* Wbase = W + (size_t)(n0 + lrow) * DIMK + lc4;
    const uint32_t sAoff  = smb + (uint32_t)(lrow * KST + lc4) * 4;
    const uint32_t sBoff  = sAoff + (uint32_t)(BM * KST) * 4;

    // prologue: chunks 0 and 1 into stages 0, 1
#pragma unroll
    for (int pc = 0; pc < 2; pc++) {
        const uint32_t sb = pc * (STGW * 4);
#pragma unroll
        for (int it = 0; it < 4; it++) {
            const int ro = it << 5;
            cp16(sAoff + sb + (uint32_t)(ro * KST) * 4, Abase + (size_t)ro * DIMK + pc * BK);
            cp16(sBoff + sb + (uint32_t)(ro * KST) * 4, Wbase + (size_t)ro * DIMK + pc * BK);
        }
        CP_COMMIT();
    }

    int scur = 0, snext = 2;
    for (int c = 0; c < 32; c++) {
        CP_WAIT(1);          // chunk c resident
        __syncthreads();     // all warps done with chunk c-1's stage (== snext)

        if (c < 30) {
            const uint32_t sb = snext * (STGW * 4);
            const int k0 = (c + 2) * BK;
#pragma unroll
            for (int it = 0; it < 4; it++) {
                const int ro = it << 5;
                cp16(sAoff + sb + (uint32_t)(ro * KST) * 4, Abase + (size_t)ro * DIMK + k0);
                cp16(sBoff + sb + (uint32_t)(ro * KST) * 4, Wbase + (size_t)ro * DIMK + k0);
            }
        }
        CP_COMMIT();         // always commit (possibly empty) to keep count

        const uint32_t* As = gsm + scur * STGW;
        const uint32_t* Bs = As + BM * KST;

#pragma unroll
        for (int ks = 0; ks < 4; ks++) {
            const int kk = ks << 3;
            uint32_t af[4][4], bf[4][2];
#pragma unroll
            for (int mt = 0; mt < 4; mt++) {
                const int rb = warpAm + (mt << 4);
                af[mt][0] = As[(rb + g    ) * KST + kk + t    ];
                af[mt][1] = As[(rb + g + 8) * KST + kk + t    ];
                af[mt][2] = As[(rb + g    ) * KST + kk + t + 4];
                af[mt][3] = As[(rb + g + 8) * KST + kk + t + 4];
            }
#pragma unroll
            for (int nt = 0; nt < 4; nt++) {
                const int nb = warpBn + (nt << 3);
                bf[nt][0] = Bs[(nb + g) * KST + kk + t    ];
                bf[nt][1] = Bs[(nb + g) * KST + kk + t + 4];
            }
#pragma unroll
            for (int mt = 0; mt < 4; mt++)
#pragma unroll
                for (int nt = 0; nt < 4; nt++)
                    mma_tf32(acc[mt][nt][0], acc[mt][nt][1],
                             acc[mt][nt][2], acc[mt][nt][3],
                             af[mt][0], af[mt][1], af[mt][2], af[mt][3],
                             bf[nt][0], bf[nt][1]);
        }

        scur = (scur == 2) ? 0 : scur + 1;
        snext = (snext == 2) ? 0 : snext + 1;
    }

#pragma unroll
    for (int nt = 0; nt < 4; nt++) {
        const int n = n0 + warpBn + (nt << 3) + (t << 1);
        const float bx = bias[n], by = bias[n + 1];
#pragma unroll
        for (int mt = 0; mt < 4; mt++) {
            const int r0 = m0 + warpAm + (mt << 4) + g;
            const int r1 = r0 + 8;
            const float v00 = acc[mt][nt][0] + bx, v01 = acc[mt][nt][1] + by;
            const float v10 = acc[mt][nt][2] + bx, v11 = acc[mt][nt][3] + by;
            if (layout == 0) {
                *(float2*)(Cf + (size_t)r0 * DIMK + n) = make_float2(v00, v01);
                *(float2*)(Cf + (size_t)r1 * DIMK + n) = make_float2(v10, v11);
            } else {
                const int h_ = n >> 6, d_ = n & 63;
                const int b0_ = r0 >> 12, s0_ = r0 & 4095;
                const int b1_ = r1 >> 12, s1_ = r1 & 4095;
                *(uint2*)(C + (((size_t)(b0_ * H + h_)) * SEQ + s0_) * HD + d_) =
                    make_uint2(f32_tf32(v00), f32_tf32(v01));
                *(uint2*)(C + (((size_t)(b1_ * H + h_)) * SEQ + s1_) * HD + d_) =
                    make_uint2(f32_tf32(v10), f32_tf32(v11));
            }
        }
    }
}

// ---------------------------------------------------------------------------
// Tensorized sliding-window attention. Q/K/V arrive as tf32 u32; staging is
// pure cp.async (no cvt, no register roundtrip). Ps aliases Ks (52 KB smem).
// ---------------------------------------------------------------------------
#define AST 68
#define VST 72
#define SMEM_AMMA ((2 * 64 * AST + 64 * VST) * 4)   // 53248 B

__global__ void __launch_bounds__(128) attn_mma()
{
    extern __shared__ __align__(16) uint32_t smu[];
    uint32_t* Qs = smu;                  // [64][AST]
    uint32_t* Ks = smu + 64 * AST;       // [64][AST] ; reused as Ps
    uint32_t* Vs = smu + 2 * 64 * AST;   // [64][VST]

    const int tid  = threadIdx.x;
    const int w    = tid >> 5;
    const int lane = tid & 31;
    const int g    = lane >> 2;
    const int t    = lane & 3;

    const int qi = blockIdx.x & 63;
    const int h  = (blockIdx.x >> 6) & 15;
    const int b  = blockIdx.x >> 10;
    const int p0 = qi << 6;

    const size_t headoff = ((size_t)(b * H + h)) * SEQ * HD;
    const uint32_t* qbase = g_q + headoff;
    const uint32_t* kbase = g_k + headoff;
    const uint32_t* vbase = g_v + headoff;

    const uint32_t smb = smem_u32(smu);
    const uint32_t Ksb = smb + (uint32_t)(64 * AST) * 4;
    const uint32_t Vsb = smb + (uint32_t)(2 * 64 * AST) * 4;

    // stage Q via cp.async
#pragma unroll
    for (int it = 0; it < 8; it++) {
        const int u = tid + (it << 7);
        const int row = u >> 4, c4 = (u & 15) << 2;
        cp16(smb + (uint32_t)(row * AST + c4) * 4, qbase + (size_t)(p0 + row) * HD + c4);
    }
    CP_COMMIT(); CP_WAIT(0);
    __syncthreads();

    const int r0 = (w << 4) + g;
    const int q0 = p0 + r0;
    const int q1 = q0 + 8;

    float O[8][4];
#pragma unroll
    for (int nt = 0; nt < 8; nt++)
#pragma unroll
        for (int r = 0; r < 4; r++) O[nt][r] = 0.f;
    float m0 = -1.0e4f, m1 = -1.0e4f, l0 = 0.f, l1 = 0.f;

    const float SC = 0.125f * 1.44269504f;   // hd^-0.5 * log2(e)

    const int ktlo = (qi >= 8) ? (qi - 8) : 0;
    for (int kt = ktlo; kt <= qi; kt++) {
        const int t0 = kt << 6;

        __syncthreads();   // prior PV reads of Ps/Vs complete
#pragma unroll
        for (int it = 0; it < 8; it++) {
            const int u = tid + (it << 7);
            const int row = u >> 4, c4 = (u & 15) << 2;
            cp16(Ksb + (uint32_t)(row * AST + c4) * 4, kbase + (size_t)(t0 + row) * HD + c4);
            cp16(Vsb + (uint32_t)(row * VST + c4) * 4, vbase + (size_t)(t0 + row) * HD + c4);
        }
        CP_COMMIT(); CP_WAIT(0);
        __syncthreads();

        // S = Q K^T
        float s[8][4];
#pragma unroll
        for (int nt = 0; nt < 8; nt++)
#pragma unroll
            for (int r = 0; r < 4; r++) s[nt][r] = 0.f;

#pragma unroll
        for (int ks = 0; ks < 8; ks++) {
            const int kk = ks << 3;
            const uint32_t a0 = Qs[r0 * AST + kk + t];
            const uint32_t a1 = Qs[(r0 + 8) * AST + kk + t];
            const uint32_t a2 = Qs[r0 * AST + kk + t + 4];
            const uint32_t a3 = Qs[(r0 + 8) * AST + kk + t + 4];
#pragma unroll
            for (int nt = 0; nt < 8; nt++) {
                const uint32_t b0 = Ks[((nt << 3) + g) * AST + kk + t];
                const uint32_t b1 = Ks[((nt << 3) + g) * AST + kk + t + 4];
                mma_tf32(s[nt][0], s[nt][1], s[nt][2], s[nt][3],
                         a0, a1, a2, a3, b0, b1);
            }
        }

        // mask + scale (log2 domain) + online softmax
        float rmax0 = -3.0e4f, rmax1 = -3.0e4f;
#pragma unroll
        for (int nt = 0; nt < 8; nt++) {
            const int c = t0 + (nt << 3) + (t << 1);
            s[nt][0] = ((unsigned)(q0 - c)     < 512u) ? s[nt][0] * SC : -3.0e4f;
            s[nt][1] = ((unsigned)(q0 - c - 1) < 512u) ? s[nt][1] * SC : -3.0e4f;
            s[nt][2] = ((unsigned)(q1 - c)     < 512u) ? s[nt][2] * SC : -3.0e4f;
            s[nt][3] = ((unsigned)(q1 - c - 1) < 512u) ? s[nt][3] * SC : -3.0e4f;
            rmax0 = fmaxf(rmax0, fmaxf(s[nt][0], s[nt][1]));
            rmax1 = fmaxf(rmax1, fmaxf(s[nt][2], s[nt][3]));
        }
        rmax0 = fmaxf(rmax0, __shfl_xor_sync(0xffffffffu, rmax0, 1));
        rmax0 = fmaxf(rmax0, __shfl_xor_sync(0xffffffffu, rmax0, 2));
        rmax1 = fmaxf(rmax1, __shfl_xor_sync(0xffffffffu, rmax1, 1));
        rmax1 = fmaxf(rmax1, __shfl_xor_sync(0xffffffffu, rmax1, 2));

        const float mn0 = fmaxf(m0, rmax0);
        const float mn1 = fmaxf(m1, rmax1);
        const float al0 = ex2f(m0 - mn0);
        const float al1 = ex2f(m1 - mn1);
        m0 = mn0; m1 = mn1;

        float rs0 = 0.f, rs1 = 0.f;
        uint2 pw0[8], pw1[8];
#pragma unroll
        for (int nt = 0; nt < 8; nt++) {
            const float p00 = ex2f(s[nt][0] - mn0);
            const float p01 = ex2f(s[nt][1] - mn0);
            const float p10 = ex2f(s[nt][2] - mn1);
            const float p11 = ex2f(s[nt][3] - mn1);
            rs0 += p00 + p01;
            rs1 += p10 + p11;
            pw0[nt] = make_uint2(f32_tf32(p00), f32_tf32(p01));
            pw1[nt] = make_uint2(f32_tf32(p10), f32_tf32(p11));
        }
        rs0 += __shfl_xor_sync(0xffffffffu, rs0, 1);
        rs0 += __shfl_xor_sync(0xffffffffu, rs0, 2);
        rs1 += __shfl_xor_sync(0xffffffffu, rs1, 1);
        rs1 += __shfl_xor_sync(0xffffffffu, rs1, 2);

        l0 = l0 * al0 + rs0;
        l1 = l1 * al1 + rs1;
#pragma unroll
        for (int nt = 0; nt < 8; nt++) {
            O[nt][0] *= al0; O[nt][1] *= al0;
            O[nt][2] *= al1; O[nt][3] *= al1;
        }

        __syncthreads();   // all warps' K-fragment reads done -> safe to alias
        uint32_t* Ps = Ks;
#pragma unroll
        for (int nt = 0; nt < 8; nt++) {
            const int cc = (nt << 3) + (t << 1);
            *(uint2*)&Ps[r0 * AST + cc]       = pw0[nt];
            *(uint2*)&Ps[(r0 + 8) * AST + cc] = pw1[nt];
        }
        __syncwarp();      // Ps rows are warp-private

        // O += P V   (V read transposed, stride 72 => conflict-free)
#pragma unroll
        for (int ks = 0; ks < 8; ks++) {
            const int kk = ks << 3;
            const uint32_t a0 = Ps[r0 * AST + kk + t];
            const uint32_t a1 = Ps[(r0 + 8) * AST + kk + t];
            const uint32_t a2 = Ps[r0 * AST + kk + t + 4];
            const uint32_t a3 = Ps[(r0 + 8) * AST + kk + t + 4];
#pragma unroll
            for (int nt = 0; nt < 8; nt++) {
                const uint32_t b0 = Vs[(kk + t) * VST + (nt << 3) + g];
                const uint32_t b1 = Vs[(kk + t + 4) * VST + (nt << 3) + g];
                mma_tf32(O[nt][0], O[nt][1], O[nt][2], O[nt][3],
                         a0, a1, a2, a3, b0, b1);
            }
        }
    }

    // epilogue: normalize, write tf32 u32 into g_att (consumed by O-proj mma)
    const float inv0 = 1.f / l0;
    const float inv1 = 1.f / l1;
    uint32_t* dst0 = g_att + ((size_t)b * SEQ + q0) * DIMK + h * HD;
    uint32_t* dst1 = g_att + ((size_t)b * SEQ + q1) * DIMK + h * HD;
#pragma unroll
    for (int nt = 0; nt < 8; nt++) {
        const int cc = (nt << 3) + (t << 1);
        *(uint2*)(dst0 + cc) = make_uint2(f32_tf32(O[nt][0] * inv0), f32_tf32(O[nt][1] * inv0));
        *(uint2*)(dst1 + cc) = make_uint2(f32_tf32(O[nt][2] * inv1), f32_tf32(O[nt][3] * inv1));
    }
}

// ---------------------------------------------------------------------------
extern "C" void kernel_launch(void* const* d_in, const int* in_sizes, int n_in,
                              void* d_out, int out_size)
{
    const float* x  = (const float*)d_in[0];
    const float* Wq = (const float*)d_in[1];
    const float* bq = (const float*)d_in[2];
    const float* Wk = (const float*)d_in[3];
    const float* bk = (const float*)d_in[4];
    const float* Wv = (const float*)d_in[5];
    const float* bv = (const float*)d_in[6];
    const float* Wo = (const float*)d_in[7];
    const float* bo = (const float*)d_in[8];
    float* out = (float*)d_out;

    uint32_t *qp, *kp, *vp, *ap, *xp, *wp;
    cudaGetSymbolAddress((void**)&qp, g_q);
    cudaGetSymbolAddress((void**)&kp, g_k);
    cudaGetSymbolAddress((void**)&vp, g_v);
    cudaGetSymbolAddress((void**)&ap, g_att);
    cudaGetSymbolAddress((void**)&xp, g_x32);
    cudaGetSymbolAddress((void**)&wp, g_w32);
    uint32_t* w0 = wp;
    uint32_t* w1 = wp + (size_t)DIMK * DIMK;
    uint32_t* w2 = wp + 2 * (size_t)DIMK * DIMK;
    uint32_t* w3 = wp + 3 * (size_t)DIMK * DIMK;

    cudaFuncSetAttribute(gemm_mma,
                         cudaFuncAttributeMaxDynamicSharedMemorySize, SM_GEMM);
    cudaFuncSetAttribute(attn_mma,
                         cudaFuncAttributeMaxDynamicSharedMemorySize, SMEM_AMMA);

    // pre-convert x and weights to tf32 bit patterns
    const int nx4 = M_TOT * DIMK / 4;       // 2,097,152
    const int nw4 = DIMK * DIMK / 4;        // 262,144
    conv_tf32<<<(nx4 + 255) / 256, 256>>>(x,  xp, nx4);
    conv_tf32<<<(nw4 + 255) / 256, 256>>>(Wq, w0, nw4);
    conv_tf32<<<(nw4 + 255) / 256, 256>>>(Wk, w1, nw4);
    conv_tf32<<<(nw4 + 255) / 256, 256>>>(Wv, w2, nw4);
    conv_tf32<<<(nw4 + 255) / 256, 256>>>(Wo, w3, nw4);

    dim3 gqkv(DIMK / BN, M_TOT / BM, 3);   // fused Q/K/V projections
    gemm_mma<<<gqkv, 256, SM_GEMM>>>(xp, w0, w1, w2, bq, bk, bv,
                                     qp, kp, vp, nullptr, 1);
    attn_mma<<<BSZ * H * (SEQ / 64), 128, SMEM_AMMA>>>();
    dim3 go(DIMK / BN, M_TOT / BM, 1);     // output projection (fp32 out)
    gemm_mma<<<go, 256, SM_GEMM>>>(ap, w3, w3, w3, bo, bo, bo,
                                   nullptr, nullptr, nullptr, out, 0);
}

// round 12
// speedup vs baseline: 1.2722x; 1.0689x over previous
#include <cuda_runtime.h>
#include <cstdint>

#define DIMK 1024
#define BSZ  2
#define SEQ  4096
#define H    16
#define HD   64
#define M_TOT (BSZ * SEQ)   // 8192

// ---------------------------------------------------------------------------
// Scratch (allocation-free). tf32 bit patterns as u32. All k-dimension
// buffers use the 8-group column permutation perm8(k) = ((k&3)<<1)|((k&4)>>2)
// so mma fragment loads become 64-bit (cols t,t+4 -> 2t,2t+1 adjacent).
// ---------------------------------------------------------------------------
__device__ uint32_t g_q[(size_t)BSZ * H * SEQ * HD];      // d-permuted
__device__ uint32_t g_k[(size_t)BSZ * H * SEQ * HD];      // d-permuted
__device__ uint32_t g_v[(size_t)BSZ * H * SEQ * HD];      // unpermuted
__device__ uint32_t g_att[(size_t)BSZ * SEQ * DIMK];      // d-permuted
__device__ uint32_t g_x32[(size_t)M_TOT * DIMK];          // k-permuted
__device__ uint32_t g_w32[4][(size_t)DIMK * DIMK];        // k-permuted

__device__ __forceinline__ int perm8(int k) { return ((k & 3) << 1) | ((k & 4) >> 2); }

__device__ __forceinline__ uint32_t f32_tf32(float f) {
    uint32_t r; asm("cvt.rna.tf32.f32 %0, %1;" : "=r"(r) : "f"(f)); return r;
}
__device__ __forceinline__ float ex2f(float x) {
    float r; asm("ex2.approx.f32 %0, %1;" : "=f"(r) : "f"(x)); return r;
}
__device__ __forceinline__ uint32_t smem_u32(const void* p) {
    uint32_t a;
    asm("{ .reg .u64 t; cvta.to.shared.u64 t, %1; cvt.u32.u64 %0, t; }" : "=r"(a) : "l"(p));
    return a;
}
__device__ __forceinline__ void cp16(uint32_t s, const void* g) {
    asm volatile("cp.async.cg.shared.global [%0], [%1], 16;" :: "r"(s), "l"(g));
}
#define CP_COMMIT()  asm volatile("cp.async.commit_group;" ::: "memory")
#define CP_WAIT(n)   asm volatile("cp.async.wait_group %0;" :: "n"(n) : "memory")

__device__ __forceinline__ void mma_tf32(float& c0, float& c1, float& c2, float& c3,
                                         uint32_t a0, uint32_t a1, uint32_t a2, uint32_t a3,
                                         uint32_t b0, uint32_t b1) {
    asm volatile("mma.sync.aligned.m16n8k8.row.col.f32.tf32.tf32.f32 "
        "{%0,%1,%2,%3}, {%4,%5,%6,%7}, {%8,%9}, {%0,%1,%2,%3};"
        : "+f"(c0), "+f"(c1), "+f"(c2), "+f"(c3)
        : "r"(a0), "r"(a1), "r"(a2), "r"(a3), "r"(b0), "r"(b1));
}

// ---------------------------------------------------------------------------
// fp32 -> tf32 with k-permutation within each 8-column group.
// Thread handles 4 consecutive cols (same group half): dst = base+off+2j.
// ---------------------------------------------------------------------------
__global__ void __launch_bounds__(256) conv_tf32(const float* __restrict__ src,
                                                 uint32_t* __restrict__ dst, int n4)
{
    const int i = blockIdx.x * blockDim.x + threadIdx.x;
    if (i < n4) {
        float4 v = ((const float4*)src)[i];
        const int c    = i << 2;
        const int base = c & ~7;
        const int off  = (c & 4) ? 1 : 0;
        dst[base + off + 0] = f32_tf32(v.x);
        dst[base + off + 2] = f32_tf32(v.y);
        dst[base + off + 4] = f32_tf32(v.z);
        dst[base + off + 6] = f32_tf32(v.w);
    }
}

// ---------------------------------------------------------------------------
// tf32 mma.sync GEMM, 2-stage cp.async pipeline, 64-bit fragment loads.
// A, W pre-converted + k-permuted. CTA 128x128, BK=32, 8 warps (2M x 4N).
// layout 1: scatter tf32 u32 -> [B,H,S,hd]; z<2 outputs d-permuted (Q,K),
//           z==2 unpermuted (V).  layout 0: fp32 row-major [M,1024].
// ---------------------------------------------------------------------------
#define BM 128
#define BN 128
#define BK 32
#define KST 40                           // 40 = 8 mod 32: LDS.64 conflict-free
#define STGW ((BM + BN) * KST)           // 10240 words / stage
#define SM_GEMM (2 * STGW * 4)           // 81920 B -> 2 CTAs/SM

__global__ void __launch_bounds__(256, 2) gemm_mma(const uint32_t* __restrict__ A,
                                                   const uint32_t* __restrict__ W0,
                                                   const uint32_t* __restrict__ W1,
                                                   const uint32_t* __restrict__ W2,
                                                   const float* __restrict__ b0p,
                                                   const float* __restrict__ b1p,
                                                   const float* __restrict__ b2p,
                                                   uint32_t* __restrict__ C0,
                                                   uint32_t* __restrict__ C1,
                                                   uint32_t* __restrict__ C2,
                                                   float* __restrict__ Cf,
                                                   int layout)
{
    extern __shared__ __align__(16) uint32_t gsm[];

    const int z = blockIdx.z;
    const uint32_t* W    = (z == 0) ? W0 : (z == 1) ? W1 : W2;
    const float*    bias = (z == 0) ? b0p : (z == 1) ? b1p : b2p;
    uint32_t*       C    = (z == 0) ? C0 : (z == 1) ? C1 : C2;

    const int tid  = threadIdx.x;
    const int wid  = tid >> 5;
    const int lane = tid & 31;
    const int g    = lane >> 2;
    const int t    = lane & 3;
    const int wm   = wid & 1;
    const int wn   = wid >> 1;
    const int m0   = blockIdx.y * BM;
    const int n0   = blockIdx.x * BN;

    const int lrow = tid >> 3;        // 0..31
    const int lc4  = (tid & 7) << 2;  // 0..28 step 4

    const uint32_t smb = smem_u32(gsm);

    float acc[4][4][4];
#pragma unroll
    for (int i = 0; i < 4; i++)
#pragma unroll
        for (int j = 0; j < 4; j++)
#pragma unroll
            for (int r = 0; r < 4; r++) acc[i][j][r] = 0.f;

    const int warpAm = wm * 64;
    const int warpBn = wn * 32;

    const uint32_t* Abase = A + (size_t)(m0 + lrow) * DIMK + lc4;
    const uint32_t* Wbase = W + (size_t)(n0 + lrow) * DIMK + lc4;
    const uint32_t sAoff  = smb + (uint32_t)(lrow * KST + lc4) * 4;
    const uint32_t sBoff  = sAoff + (uint32_t)(BM * KST) * 4;

    // prologue: chunk 0 into stage 0
#pragma unroll
    for (int it = 0; it < 4; it++) {
        const int ro = it << 5;
        cp16(sAoff + (uint32_t)(ro * KST) * 4, Abase + (size_t)ro * DIMK);
        cp16(sBoff + (uint32_t)(ro * KST) * 4, Wbase + (size_t)ro * DIMK);
    }
    CP_COMMIT();

    for (int c = 0; c < 32; c++) {
        CP_WAIT(0);          // chunk c resident
        __syncthreads();     // all warps done reading chunk c-1's stage

        if (c < 31) {
            const uint32_t sb = ((c + 1) & 1) * (uint32_t)(STGW * 4);
            const int k0 = (c + 1) * BK;
#pragma unroll
            for (int it = 0; it < 4; it++) {
                const int ro = it << 5;
                cp16(sAoff + sb + (uint32_t)(ro * KST) * 4, Abase + (size_t)ro * DIMK + k0);
                cp16(sBoff + sb + (uint32_t)(ro * KST) * 4, Wbase + (size_t)ro * DIMK + k0);
            }
            CP_COMMIT();     // overlaps this chunk's MMA
        }

        const uint32_t* As = gsm + (c & 1) * STGW;
        const uint32_t* Bs = As + BM * KST;

#pragma unroll
        for (int ks = 0; ks < 4; ks++) {
            const int kk = (ks << 3) + (t << 1);   // permuted: cols t,t+4 at 2t,2t+1
            uint2 al[4], ah[4], bb[4];
#pragma unroll
            for (int mt = 0; mt < 4; mt++) {
                const int rb = warpAm + (mt << 4);
                al[mt] = *(const uint2*)&As[(rb + g    ) * KST + kk];
                ah[mt] = *(const uint2*)&As[(rb + g + 8) * KST + kk];
            }
#pragma unroll
            for (int nt = 0; nt < 4; nt++) {
                const int nb = warpBn + (nt << 3);
                bb[nt] = *(const uint2*)&Bs[(nb + g) * KST + kk];
            }
#pragma unroll
            for (int mt = 0; mt < 4; mt++)
#pragma unroll
                for (int nt = 0; nt < 4; nt++)
                    mma_tf32(acc[mt][nt][0], acc[mt][nt][1],
                             acc[mt][nt][2], acc[mt][nt][3],
                             al[mt].x, ah[mt].x, al[mt].y, ah[mt].y,
                             bb[nt].x, bb[nt].y);
        }
    }

#pragma unroll
    for (int nt = 0; nt < 4; nt++) {
        const int n = n0 + warpBn + (nt << 3) + (t << 1);
        const float bx = bias[n], by = bias[n + 1];
#pragma unroll
        for (int mt = 0; mt < 4; mt++) {
            const int r0 = m0 + warpAm + (mt << 4) + g;
            const int r1 = r0 + 8;
            const float v00 = acc[mt][nt][0] + bx, v01 = acc[mt][nt][1] + by;
            const float v10 = acc[mt][nt][2] + bx, v11 = acc[mt][nt][3] + by;
            if (layout == 0) {
                *(float2*)(Cf + (size_t)r0 * DIMK + n) = make_float2(v00, v01);
                *(float2*)(Cf + (size_t)r1 * DIMK + n) = make_float2(v10, v11);
            } else {
                const int h_ = n >> 6, d_ = n & 63;
                const int b0_ = r0 >> 12, s0_ = r0 & 4095;
                const int b1_ = r1 >> 12, s1_ = r1 & 4095;
                uint32_t* p0 = C + (((size_t)(b0_ * H + h_)) * SEQ + s0_) * HD;
                uint32_t* p1 = C + (((size_t)(b1_ * H + h_)) * SEQ + s1_) * HD;
                if (z < 2) {   // Q,K: store d-permuted
                    const int pc0 = (d_ & ~7) | perm8(d_ & 7);
                    const int pc1 = (d_ & ~7) | perm8((d_ & 7) + 1);
                    p0[pc0] = f32_tf32(v00); p0[pc1] = f32_tf32(v01);
                    p1[pc0] = f32_tf32(v10); p1[pc1] = f32_tf32(v11);
                } else {       // V: unpermuted
                    *(uint2*)(p0 + d_) = make_uint2(f32_tf32(v00), f32_tf32(v01));
                    *(uint2*)(p1 + d_) = make_uint2(f32_tf32(v10), f32_tf32(v11));
                }
            }
        }
    }
}

// ---------------------------------------------------------------------------
// Tensorized sliding-window attention, 64-bit fragment loads.
// Q/K arrive d-permuted; V staged with row-permutation; P stored at permuted
// columns. Ps aliases Ks. AST=72 (LDS.64 conflict-free), VST=68 (2*68=8 mod 32).
// ---------------------------------------------------------------------------
#define AST 72
#define VST 68
#define SMEM_AMMA ((2 * 64 * AST + 64 * VST) * 4)   // 54272 B -> 4 CTAs/SM

__global__ void __launch_bounds__(128) attn_mma()
{
    extern __shared__ __align__(16) uint32_t smu[];
    uint32_t* Qs = smu;                  // [64][AST]
    uint32_t* Ks = smu + 64 * AST;       // [64][AST] ; reused as Ps
    uint32_t* Vs = smu + 2 * 64 * AST;   // [64][VST] row-permuted

    const int tid  = threadIdx.x;
    const int w    = tid >> 5;
    const int lane = tid & 31;
    const int g    = lane >> 2;
    const int t    = lane & 3;

    const int qi = blockIdx.x & 63;
    const int h  = (blockIdx.x >> 6) & 15;
    const int b  = blockIdx.x >> 10;
    const int p0 = qi << 6;

    const size_t headoff = ((size_t)(b * H + h)) * SEQ * HD;
    const uint32_t* qbase = g_q + headoff;
    const uint32_t* kbase = g_k + headoff;
    const uint32_t* vbase = g_v + headoff;

    const uint32_t smb = smem_u32(smu);
    const uint32_t Ksb = smb + (uint32_t)(64 * AST) * 4;
    const uint32_t Vsb = smb + (uint32_t)(2 * 64 * AST) * 4;

    // stage Q (already permuted in d)
#pragma unroll
    for (int it = 0; it < 8; it++) {
        const int u = tid + (it << 7);
        const int row = u >> 4, c4 = (u & 15) << 2;
        cp16(smb + (uint32_t)(row * AST + c4) * 4, qbase + (size_t)(p0 + row) * HD + c4);
    }
    CP_COMMIT(); CP_WAIT(0);
    __syncthreads();

    const int r0 = (w << 4) + g;
    const int q0 = p0 + r0;
    const int q1 = q0 + 8;
    const int pc0 = perm8(t << 1);         // {0,4,1,5}
    const int pc1 = perm8((t << 1) + 1);   // {2,6,3,7}

    float O[8][4];
#pragma unroll
    for (int nt = 0; nt < 8; nt++)
#pragma unroll
        for (int r = 0; r < 4; r++) O[nt][r] = 0.f;
    float m0 = -1.0e4f, m1 = -1.0e4f, l0 = 0.f, l1 = 0.f;

    const float SC = 0.125f * 1.44269504f;   // hd^-0.5 * log2(e)

    const int ktlo = (qi >= 8) ? (qi - 8) : 0;
    for (int kt = ktlo; kt <= qi; kt++) {
        const int t0 = kt << 6;

        __syncthreads();   // prior PV reads of Ps/Vs complete
#pragma unroll
        for (int it = 0; it < 8; it++) {
            const int u = tid + (it << 7);
            const int row = u >> 4, c4 = (u & 15) << 2;
            const int pr = (row & ~7) | perm8(row & 7);   // V row permutation
            cp16(Ksb + (uint32_t)(row * AST + c4) * 4, kbase + (size_t)(t0 + row) * HD + c4);
            cp16(Vsb + (uint32_t)(pr  * VST + c4) * 4, vbase + (size_t)(t0 + row) * HD + c4);
        }
        CP_COMMIT(); CP_WAIT(0);
        __syncthreads();

        // S = Q K^T  (64-bit fragment loads, permuted k)
        float s[8][4];
#pragma unroll
        for (int nt = 0; nt < 8; nt++)
#pragma unroll
            for (int r = 0; r < 4; r++) s[nt][r] = 0.f;

#pragma unroll
        for (int ks = 0; ks < 8; ks++) {
            const int kk = (ks << 3) + (t << 1);
            const uint2 ql = *(const uint2*)&Qs[r0 * AST + kk];
            const uint2 qh = *(const uint2*)&Qs[(r0 + 8) * AST + kk];
#pragma unroll
            for (int nt = 0; nt < 8; nt++) {
                const uint2 kb = *(const uint2*)&Ks[((nt << 3) + g) * AST + kk];
                mma_tf32(s[nt][0], s[nt][1], s[nt][2], s[nt][3],
                         ql.x, qh.x, ql.y, qh.y, kb.x, kb.y);
            }
        }

        // mask + scale (log2 domain) + online softmax
        float rmax0 = -3.0e4f, rmax1 = -3.0e4f;
#pragma unroll
        for (int nt = 0; nt < 8; nt++) {
            const int c = t0 + (nt << 3) + (t << 1);
            s[nt][0] = ((unsigned)(q0 - c)     < 512u) ? s[nt][0] * SC : -3.0e4f;
            s[nt][1] = ((unsigned)(q0 - c - 1) < 512u) ? s[nt][1] * SC : -3.0e4f;
            s[nt][2] = ((unsigned)(q1 - c)     < 512u) ? s[nt][2] * SC : -3.0e4f;
            s[nt][3] = ((unsigned)(q1 - c - 1) < 512u) ? s[nt][3] * SC : -3.0e4f;
            rmax0 = fmaxf(rmax0, fmaxf(s[nt][0], s[nt][1]));
            rmax1 = fmaxf(rmax1, fmaxf(s[nt][2], s[nt][3]));
        }
        rmax0 = fmaxf(rmax0, __shfl_xor_sync(0xffffffffu, rmax0, 1));
        rmax0 = fmaxf(rmax0, __shfl_xor_sync(0xffffffffu, rmax0, 2));
        rmax1 = fmaxf(rmax1, __shfl_xor_sync(0xffffffffu, rmax1, 1));
        rmax1 = fmaxf(rmax1, __shfl_xor_sync(0xffffffffu, rmax1, 2));

        const float mn0 = fmaxf(m0, rmax0);
        const float mn1 = fmaxf(m1, rmax1);
        const float al0 = ex2f(m0 - mn0);
        const float al1 = ex2f(m1 - mn1);
        m0 = mn0; m1 = mn1;

        float rs0 = 0.f, rs1 = 0.f;
        uint2 pw0[8], pw1[8];
#pragma unroll
        for (int nt = 0; nt < 8; nt++) {
            const float p00 = ex2f(s[nt][0] - mn0);
            const float p01 = ex2f(s[nt][1] - mn0);
            const float p10 = ex2f(s[nt][2] - mn1);
            const float p11 = ex2f(s[nt][3] - mn1);
            rs0 += p00 + p01;
            rs1 += p10 + p11;
            pw0[nt] = make_uint2(f32_tf32(p00), f32_tf32(p01));
            pw1[nt] = make_uint2(f32_tf32(p10), f32_tf32(p11));
        }
        rs0 += __shfl_xor_sync(0xffffffffu, rs0, 1);
        rs0 += __shfl_xor_sync(0xffffffffu, rs0, 2);
        rs1 += __shfl_xor_sync(0xffffffffu, rs1, 1);
        rs1 += __shfl_xor_sync(0xffffffffu, rs1, 2);

        l0 = l0 * al0 + rs0;
        l1 = l1 * al1 + rs1;
#pragma unroll
        for (int nt = 0; nt < 8; nt++) {
            O[nt][0] *= al0; O[nt][1] *= al0;
            O[nt][2] *= al1; O[nt][3] *= al1;
        }

        __syncthreads();   // all warps' K-fragment reads done -> safe to alias
        uint32_t* Ps = Ks;
#pragma unroll
        for (int nt = 0; nt < 8; nt++) {   // store P at permuted key columns
            const int nb = nt << 3;
            Ps[r0 * AST + nb + pc0]       = pw0[nt].x;
            Ps[r0 * AST + nb + pc1]       = pw0[nt].y;
            Ps[(r0 + 8) * AST + nb + pc0] = pw1[nt].x;
            Ps[(r0 + 8) * AST + nb + pc1] = pw1[nt].y;
        }
        __syncwarp();      // Ps rows are warp-private

        // O += P V   (P a-frags 64-bit; V rows permuted to match)
#pragma unroll
        for (int ks = 0; ks < 8; ks++) {
            const int kk = (ks << 3) + (t << 1);
            const uint2 pl = *(const uint2*)&Ps[r0 * AST + kk];
            const uint2 ph = *(const uint2*)&Ps[(r0 + 8) * AST + kk];
#pragma unroll
            for (int nt = 0; nt < 8; nt++) {
                const uint32_t b0 = Vs[kk * VST + (nt << 3) + g];
                const uint32_t b1 = Vs[(kk + 1) * VST + (nt << 3) + g];
                mma_tf32(O[nt][0], O[nt][1], O[nt][2], O[nt][3],
                         pl.x, ph.x, pl.y, ph.y, b0, b1);
            }
        }
    }

    // epilogue: normalize, write d-permuted tf32 u32 (consumed by O-proj)
    const float inv0 = 1.f / l0;
    const float inv1 = 1.f / l1;
    uint32_t* dst0 = g_att + ((size_t)b * SEQ + q0) * DIMK + h * HD;
    uint32_t* dst1 = g_att + ((size_t)b * SEQ + q1) * DIMK + h * HD;
#pragma unroll
    for (int nt = 0; nt < 8; nt++) {
        const int nb = nt << 3;
        dst0[nb + pc0] = f32_tf32(O[nt][0] * inv0);
        dst0[nb + pc1] = f32_tf32(O[nt][1] * inv0);
        dst1[nb + pc0] = f32_tf32(O[nt][2] * inv1);
        dst1[nb + pc1] = f32_tf32(O[nt][3] * inv1);
    }
}

// ---------------------------------------------------------------------------
extern "C" void kernel_launch(void* const* d_in, const int* in_sizes, int n_in,
                              void* d_out, int out_size)
{
    const float* x  = (const float*)d_in[0];
    const float* Wq = (const float*)d_in[1];
    const float* bq = (const float*)d_in[2];
    const float* Wk = (const float*)d_in[3];
    const float* bk = (const float*)d_in[4];
    const float* Wv = (const float*)d_in[5];
    const float* bv = (const float*)d_in[6];
    const float* Wo = (const float*)d_in[7];
    const float* bo = (const float*)d_in[8];
    float* out = (float*)d_out;

    uint32_t *qp, *kp, *vp, *ap, *xp, *wp;
    cudaGetSymbolAddress((void**)&qp, g_q);
    cudaGetSymbolAddress((void**)&kp, g_k);
    cudaGetSymbolAddress((void**)&vp, g_v);
    cudaGetSymbolAddress((void**)&ap, g_att);
    cudaGetSymbolAddress((void**)&xp, g_x32);
    cudaGetSymbolAddress((void**)&wp, g_w32);
    uint32_t* w0 = wp;
    uint32_t* w1 = wp + (size_t)DIMK * DIMK;
    uint32_t* w2 = wp + 2 * (size_t)DIMK * DIMK;
    uint32_t* w3 = wp + 3 * (size_t)DIMK * DIMK;

    cudaFuncSetAttribute(gemm_mma,
                         cudaFuncAttributeMaxDynamicSharedMemorySize, SM_GEMM);
    cudaFuncSetAttribute(attn_mma,
                         cudaFuncAttributeMaxDynamicSharedMemorySize, SMEM_AMMA);

    // pre-convert (k-permuted) x and weights
    const int nx4 = M_TOT * DIMK / 4;
    const int nw4 = DIMK * DIMK / 4;
    conv_tf32<<<(nx4 + 255) / 256, 256>>>(x,  xp, nx4);
    conv_tf32<<<(nw4 + 255) / 256, 256>>>(Wq, w0, nw4);
    conv_tf32<<<(nw4 + 255) / 256, 256>>>(Wk, w1, nw4);
    conv_tf32<<<(nw4 + 255) / 256, 256>>>(Wv, w2, nw4);
    conv_tf32<<<(nw4 + 255) / 256, 256>>>(Wo, w3, nw4);

    dim3 gqkv(DIMK / BN, M_TOT / BM, 3);   // fused Q/K/V projections
    gemm_mma<<<gqkv, 256, SM_GEMM>>>(xp, w0, w1, w2, bq, bk, bv,
                                     qp, kp, vp, nullptr, 1);
    attn_mma<<<BSZ * H * (SEQ / 64), 128, SMEM_AMMA>>>();
    dim3 go(DIMK / BN, M_TOT / BM, 1);     // output projection (fp32 out)
    gemm_mma<<<go, 256, SM_GEMM>>>(ap, w3, w3, w3, bo, bo, bo,
                                   nullptr, nullptr, nullptr, out, 0);
}

// round 13
// speedup vs baseline: 1.2784x; 1.0049x over previous
#include <cuda_runtime.h>
#include <cstdint>

#define DIMK 1024
#define BSZ  2
#define SEQ  4096
#define H    16
#define HD   64
#define M_TOT (BSZ * SEQ)   // 8192

// ---------------------------------------------------------------------------
// Scratch (allocation-free). tf32 bit patterns as u32. k-dimension buffers use
// perm8(k) = ((k&3)<<1)|((k&4)>>2) within each 8-group so mma fragment loads
// (cols t, t+4) become adjacent 64-bit loads.
// ---------------------------------------------------------------------------
__device__ uint32_t g_q[(size_t)BSZ * H * SEQ * HD];      // d-permuted
__device__ uint32_t g_k[(size_t)BSZ * H * SEQ * HD];      // d-permuted
__device__ uint32_t g_v[(size_t)BSZ * H * SEQ * HD];      // unpermuted
__device__ uint32_t g_att[(size_t)BSZ * SEQ * DIMK];      // d-permuted
__device__ uint32_t g_x32[(size_t)M_TOT * DIMK];          // k-permuted
__device__ uint32_t g_w32[4][(size_t)DIMK * DIMK];        // k-permuted

__device__ __forceinline__ int perm8(int k) { return ((k & 3) << 1) | ((k & 4) >> 2); }

__device__ __forceinline__ uint32_t f32_tf32(float f) {
    uint32_t r; asm("cvt.rna.tf32.f32 %0, %1;" : "=r"(r) : "f"(f)); return r;
}
__device__ __forceinline__ float ex2f(float x) {
    float r; asm("ex2.approx.f32 %0, %1;" : "=f"(r) : "f"(x)); return r;
}
__device__ __forceinline__ uint32_t smem_u32(const void* p) {
    uint32_t a;
    asm("{ .reg .u64 t; cvta.to.shared.u64 t, %1; cvt.u32.u64 %0, t; }" : "=r"(a) : "l"(p));
    return a;
}
__device__ __forceinline__ void cp16(uint32_t s, const void* g) {
    asm volatile("cp.async.cg.shared.global [%0], [%1], 16;" :: "r"(s), "l"(g));
}
#define CP_COMMIT()  asm volatile("cp.async.commit_group;" ::: "memory")
#define CP_WAIT(n)   asm volatile("cp.async.wait_group %0;" :: "n"(n) : "memory")

__device__ __forceinline__ void mma_tf32(float& c0, float& c1, float& c2, float& c3,
                                         uint32_t a0, uint32_t a1, uint32_t a2, uint32_t a3,
                                         uint32_t b0, uint32_t b1) {
    asm volatile("mma.sync.aligned.m16n8k8.row.col.f32.tf32.tf32.f32 "
        "{%0,%1,%2,%3}, {%4,%5,%6,%7}, {%8,%9}, {%0,%1,%2,%3};"
        : "+f"(c0), "+f"(c1), "+f"(c2), "+f"(c3)
        : "r"(a0), "r"(a1), "r"(a2), "r"(a3), "r"(b0), "r"(b1));
}

// ---------------------------------------------------------------------------
// fp32 -> tf32 with k-permutation. conv_x for activations; conv_w does all 4
// weight matrices in one launch (blockIdx.y selects source).
// ---------------------------------------------------------------------------
__device__ __forceinline__ void conv4(const float* __restrict__ src,
                                      uint32_t* __restrict__ dst, int i) {
    float4 v = ((const float4*)src)[i];
    const int c    = i << 2;
    const int base = c & ~7;
    const int off  = (c & 4) ? 1 : 0;
    dst[base + off + 0] = f32_tf32(v.x);
    dst[base + off + 2] = f32_tf32(v.y);
    dst[base + off + 4] = f32_tf32(v.z);
    dst[base + off + 6] = f32_tf32(v.w);
}

__global__ void __launch_bounds__(256) conv_x(const float* __restrict__ src,
                                              uint32_t* __restrict__ dst, int n4)
{
    const int i = blockIdx.x * blockDim.x + threadIdx.x;
    if (i < n4) conv4(src, dst, i);
}

__global__ void __launch_bounds__(256) conv_w(const float* __restrict__ s0,
                                              const float* __restrict__ s1,
                                              const float* __restrict__ s2,
                                              const float* __restrict__ s3,
                                              uint32_t* __restrict__ dst)
{
    const int z = blockIdx.y;
    const float* src = (z == 0) ? s0 : (z == 1) ? s1 : (z == 2) ? s2 : s3;
    const int i = blockIdx.x * blockDim.x + threadIdx.x;
    conv4(src, dst + (size_t)z * DIMK * DIMK, i);   // grid sized exactly
}

// ---------------------------------------------------------------------------
// tf32 mma.sync GEMM: CTA 128x128, 4 warps (2M x 2N), warp tile 64x64.
// 2-stage cp.async, 64-bit fragment loads. Halved crossbar traffic vs 8-warp.
// layout 1: scatter tf32 u32 -> [B,H,S,hd] (z<2 d-permuted, z==2 plain);
// layout 0: fp32 row-major.
// ---------------------------------------------------------------------------
#define BM 128
#define BN 128
#define BK 32
#define KST 40                           // 8 mod 32: LDS.64 conflict-free
#define STGW ((BM + BN) * KST)           // 10240 words / stage
#define SM_GEMM (2 * STGW * 4)           // 81920 B -> 2 CTAs/SM

__global__ void __launch_bounds__(128, 2) gemm_mma(const uint32_t* __restrict__ A,
                                                   const uint32_t* __restrict__ W0,
                                                   const uint32_t* __restrict__ W1,
                                                   const uint32_t* __restrict__ W2,
                                                   const float* __restrict__ b0p,
                                                   const float* __restrict__ b1p,
                                                   const float* __restrict__ b2p,
                                                   uint32_t* __restrict__ C0,
                                                   uint32_t* __restrict__ C1,
                                                   uint32_t* __restrict__ C2,
                                                   float* __restrict__ Cf,
                                                   int layout)
{
    extern __shared__ __align__(16) uint32_t gsm[];

    const int z = blockIdx.z;
    const uint32_t* W    = (z == 0) ? W0 : (z == 1) ? W1 : W2;
    const float*    bias = (z == 0) ? b0p : (z == 1) ? b1p : b2p;
    uint32_t*       C    = (z == 0) ? C0 : (z == 1) ? C1 : C2;

    const int tid  = threadIdx.x;
    const int wid  = tid >> 5;
    const int lane = tid & 31;
    const int g    = lane >> 2;
    const int t    = lane & 3;
    const int wm   = wid & 1;
    const int wn   = wid >> 1;
    const int m0   = blockIdx.y * BM;
    const int n0   = blockIdx.x * BN;

    const int lrow = tid >> 3;        // 0..15
    const int lc4  = (tid & 7) << 2;  // 0..28 step 4

    const uint32_t smb = smem_u32(gsm);

    float acc[4][8][4];
#pragma unroll
    for (int i = 0; i < 4; i++)
#pragma unroll
        for (int j = 0; j < 8; j++)
#pragma unroll
            for (int r = 0; r < 4; r++) acc[i][j][r] = 0.f;

    const int warpAm = wm * 64;
    const int warpBn = wn * 64;

    const uint32_t* Abase = A + (size_t)(m0 + lrow) * DIMK + lc4;
    const uint32_t* Wbase = W + (size_t)(n0 + lrow) * DIMK + lc4;
    const uint32_t sAoff  = smb + (uint32_t)(lrow * KST + lc4) * 4;
    const uint32_t sBoff  = sAoff + (uint32_t)(BM * KST) * 4;

    // prologue: chunk 0 into stage 0 (128 rows A + 128 rows W, 16 rows/iter)
#pragma unroll
    for (int it = 0; it < 8; it++) {
        const int ro = it << 4;
        cp16(sAoff + (uint32_t)(ro * KST) * 4, Abase + (size_t)ro * DIMK);
        cp16(sBoff + (uint32_t)(ro * KST) * 4, Wbase + (size_t)ro * DIMK);
    }
    CP_COMMIT();

    for (int c = 0; c < 32; c++) {
        CP_WAIT(0);          // chunk c resident
        __syncthreads();     // all warps done reading chunk c-1's stage

        if (c < 31) {
            const uint32_t sb = ((c + 1) & 1) * (uint32_t)(STGW * 4);
            const int k0 = (c + 1) * BK;
#pragma unroll
            for (int it = 0; it < 8; it++) {
                const int ro = it << 4;
                cp16(sAoff + sb + (uint32_t)(ro * KST) * 4, Abase + (size_t)ro * DIMK + k0);
                cp16(sBoff + sb + (uint32_t)(ro * KST) * 4, Wbase + (size_t)ro * DIMK + k0);
            }
            CP_COMMIT();     // overlaps this chunk's MMA
        }

        const uint32_t* As = gsm + (c & 1) * STGW;
        const uint32_t* Bs = As + BM * KST;

#pragma unroll
        for (int ks = 0; ks < 4; ks++) {
            const int kk = (ks << 3) + (t << 1);   // permuted cols t,t+4 adjacent
            uint2 al[4], ah[4], bb[8];
#pragma unroll
            for (int mt = 0; mt < 4; mt++) {
                const int rb = warpAm + (mt << 4);
                al[mt] = *(const uint2*)&As[(rb + g    ) * KST + kk];
                ah[mt] = *(const uint2*)&As[(rb + g + 8) * KST + kk];
            }
#pragma unroll
            for (int nt = 0; nt < 8; nt++) {
                const int nb = warpBn + (nt << 3);
                bb[nt] = *(const uint2*)&Bs[(nb + g) * KST + kk];
            }
#pragma unroll
            for (int mt = 0; mt < 4; mt++)
#pragma unroll
                for (int nt = 0; nt < 8; nt++)
                    mma_tf32(acc[mt][nt][0], acc[mt][nt][1],
                             acc[mt][nt][2], acc[mt][nt][3],
                             al[mt].x, ah[mt].x, al[mt].y, ah[mt].y,
                             bb[nt].x, bb[nt].y);
        }
    }

#pragma unroll
    for (int nt = 0; nt < 8; nt++) {
        const int n = n0 + warpBn + (nt << 3) + (t << 1);
        const float bx = bias[n], by = bias[n + 1];
#pragma unroll
        for (int mt = 0; mt < 4; mt++) {
            const int r0 = m0 + warpAm + (mt << 4) + g;
            const int r1 = r0 + 8;
            const float v00 = acc[mt][nt][0] + bx, v01 = acc[mt][nt][1] + by;
            const float v10 = acc[mt][nt][2] + bx, v11 = acc[mt][nt][3] + by;
            if (layout == 0) {
                *(float2*)(Cf + (size_t)r0 * DIMK + n) = make_float2(v00, v01);
                *(float2*)(Cf + (size_t)r1 * DIMK + n) = make_float2(v10, v11);
            } else {
                const int h_ = n >> 6, d_ = n & 63;
                const int b0_ = r0 >> 12, s0_ = r0 & 4095;
                const int b1_ = r1 >> 12, s1_ = r1 & 4095;
                uint32_t* p0 = C + (((size_t)(b0_ * H + h_)) * SEQ + s0_) * HD;
                uint32_t* p1 = C + (((size_t)(b1_ * H + h_)) * SEQ + s1_) * HD;
                if (z < 2) {   // Q,K: d-permuted
                    const int pc0 = (d_ & ~7) | perm8(d_ & 7);
                    const int pc1 = (d_ & ~7) | perm8((d_ & 7) + 1);
                    p0[pc0] = f32_tf32(v00); p0[pc1] = f32_tf32(v01);
                    p1[pc0] = f32_tf32(v10); p1[pc1] = f32_tf32(v11);
                } else {       // V: unpermuted
                    *(uint2*)(p0 + d_) = make_uint2(f32_tf32(v00), f32_tf32(v01));
                    *(uint2*)(p1 + d_) = make_uint2(f32_tf32(v10), f32_tf32(v11));
                }
            }
        }
    }
}

// ---------------------------------------------------------------------------
// Tensorized sliding-window attention. Q fragments hoisted to registers;
// Ps aliases the (dead) Qs buffer => only 2 barriers per key tile; P stored
// inline during softmax. 64-bit fragment loads throughout.
// ---------------------------------------------------------------------------
#define AST 72
#define VST 68
#define SMEM_AMMA ((2 * 64 * AST + 64 * VST) * 4)   // 54272 B -> 4 CTAs/SM

__global__ void __launch_bounds__(128, 4) attn_mma()
{
    extern __shared__ __align__(16) uint32_t smu[];
    uint32_t* Qs = smu;                  // [64][AST] ; dead after prologue -> Ps
    uint32_t* Ks = smu + 64 * AST;       // [64][AST]
    uint32_t* Vs = smu + 2 * 64 * AST;   // [64][VST] row-permuted

    const int tid  = threadIdx.x;
    const int w    = tid >> 5;
    const int lane = tid & 31;
    const int g    = lane >> 2;
    const int t    = lane & 3;

    const int qi = blockIdx.x & 63;
    const int h  = (blockIdx.x >> 6) & 15;
    const int b  = blockIdx.x >> 10;
    const int p0 = qi << 6;

    const size_t headoff = ((size_t)(b * H + h)) * SEQ * HD;
    const uint32_t* qbase = g_q + headoff;
    const uint32_t* kbase = g_k + headoff;
    const uint32_t* vbase = g_v + headoff;

    const uint32_t smb = smem_u32(smu);
    const uint32_t Ksb = smb + (uint32_t)(64 * AST) * 4;
    const uint32_t Vsb = smb + (uint32_t)(2 * 64 * AST) * 4;

    // stage Q, then hoist this warp's fragments into registers
#pragma unroll
    for (int it = 0; it < 8; it++) {
        const int u = tid + (it << 7);
        const int row = u >> 4, c4 = (u & 15) << 2;
        cp16(smb + (uint32_t)(row * AST + c4) * 4, qbase + (size_t)(p0 + row) * HD + c4);
    }
    CP_COMMIT(); CP_WAIT(0);
    __syncthreads();

    const int r0 = (w << 4) + g;
    const int q0 = p0 + r0;
    const int q1 = q0 + 8;
    const int pc0 = perm8(t << 1);
    const int pc1 = perm8((t << 1) + 1);

    uint2 qfl[8], qfh[8];
#pragma unroll
    for (int ks = 0; ks < 8; ks++) {
        const int kk = (ks << 3) + (t << 1);
        qfl[ks] = *(const uint2*)&Qs[r0 * AST + kk];
        qfh[ks] = *(const uint2*)&Qs[(r0 + 8) * AST + kk];
    }
    __syncthreads();   // Qs now dead -> becomes Ps
    uint32_t* Ps = Qs;

    float O[8][4];
#pragma unroll
    for (int nt = 0; nt < 8; nt++)
#pragma unroll
        for (int r = 0; r < 4; r++) O[nt][r] = 0.f;
    float m0 = -1.0e4f, m1 = -1.0e4f, l0 = 0.f, l1 = 0.f;

    const float SC = 0.125f * 1.44269504f;   // hd^-0.5 * log2(e)

    const int ktlo = (qi >= 8) ? (qi - 8) : 0;
    for (int kt = ktlo; kt <= qi; kt++) {
        const int t0 = kt << 6;

        __syncthreads();   // prior QK reads of Ks + PV reads of Vs complete
#pragma unroll
        for (int it = 0; it < 8; it++) {
            const int u = tid + (it << 7);
            const int row = u >> 4, c4 = (u & 15) << 2;
            const int pr = (row & ~7) | perm8(row & 7);   // V row permutation
            cp16(Ksb + (uint32_t)(row * AST + c4) * 4, kbase + (size_t)(t0 + row) * HD + c4);
            cp16(Vsb + (uint32_t)(pr  * VST + c4) * 4, vbase + (size_t)(t0 + row) * HD + c4);
        }
        CP_COMMIT(); CP_WAIT(0);
        __syncthreads();

        // S = Q K^T  (Q from registers)
        float s[8][4];
#pragma unroll
        for (int nt = 0; nt < 8; nt++)
#pragma unroll
            for (int r = 0; r < 4; r++) s[nt][r] = 0.f;

#pragma unroll
        for (int ks = 0; ks < 8; ks++) {
            const int kk = (ks << 3) + (t << 1);
#pragma unroll
            for (int nt = 0; nt < 8; nt++) {
                const uint2 kb = *(const uint2*)&Ks[((nt << 3) + g) * AST + kk];
                mma_tf32(s[nt][0], s[nt][1], s[nt][2], s[nt][3],
                         qfl[ks].x, qfh[ks].x, qfl[ks].y, qfh[ks].y, kb.x, kb.y);
            }
        }

        // mask + scale (log2 domain) + online softmax, P stored inline
        float rmax0 = -3.0e4f, rmax1 = -3.0e4f;
#pragma unroll
        for (int nt = 0; nt < 8; nt++) {
            const int c = t0 + (nt << 3) + (t << 1);
            s[nt][0] = ((unsigned)(q0 - c)     < 512u) ? s[nt][0] * SC : -3.0e4f;
            s[nt][1] = ((unsigned)(q0 - c - 1) < 512u) ? s[nt][1] * SC : -3.0e4f;
            s[nt][2] = ((unsigned)(q1 - c)     < 512u) ? s[nt][2] * SC : -3.0e4f;
            s[nt][3] = ((unsigned)(q1 - c - 1) < 512u) ? s[nt][3] * SC : -3.0e4f;
            rmax0 = fmaxf(rmax0, fmaxf(s[nt][0], s[nt][1]));
            rmax1 = fmaxf(rmax1, fmaxf(s[nt][2], s[nt][3]));
        }
        rmax0 = fmaxf(rmax0, __shfl_xor_sync(0xffffffffu, rmax0, 1));
        rmax0 = fmaxf(rmax0, __shfl_xor_sync(0xffffffffu, rmax0, 2));
        rmax1 = fmaxf(rmax1, __shfl_xor_sync(0xffffffffu, rmax1, 1));
        rmax1 = fmaxf(rmax1, __shfl_xor_sync(0xffffffffu, rmax1, 2));

        const float mn0 = fmaxf(m0, rmax0);
        const float mn1 = fmaxf(m1, rmax1);
        const float al0 = ex2f(m0 - mn0);
        const float al1 = ex2f(m1 - mn1);
        m0 = mn0; m1 = mn1;

        float rs0 = 0.f, rs1 = 0.f;
#pragma unroll
        for (int nt = 0; nt < 8; nt++) {
            const float p00 = ex2f(s[nt][0] - mn0);
            const float p01 = ex2f(s[nt][1] - mn0);
            const float p10 = ex2f(s[nt][2] - mn1);
            const float p11 = ex2f(s[nt][3] - mn1);
            rs0 += p00 + p01;
            rs1 += p10 + p11;
            const int nb = nt << 3;
            Ps[r0 * AST + nb + pc0]       = f32_tf32(p00);
            Ps[r0 * AST + nb + pc1]       = f32_tf32(p01);
            Ps[(r0 + 8) * AST + nb + pc0] = f32_tf32(p10);
            Ps[(r0 + 8) * AST + nb + pc1] = f32_tf32(p11);
        }
        rs0 += __shfl_xor_sync(0xffffffffu, rs0, 1);
        rs0 += __shfl_xor_sync(0xffffffffu, rs0, 2);
        rs1 += __shfl_xor_sync(0xffffffffu, rs1, 1);
        rs1 += __shfl_xor_sync(0xffffffffu, rs1, 2);

        l0 = l0 * al0 + rs0;
        l1 = l1 * al1 + rs1;
#pragma unroll
        for (int nt = 0; nt < 8; nt++) {
            O[nt][0] *= al0; O[nt][1] *= al0;
            O[nt][2] *= al1; O[nt][3] *= al1;
        }
        __syncwarp();      // Ps rows are warp-private

        // O += P V
#pragma unroll
        for (int ks = 0; ks < 8; ks++) {
            const int kk = (ks << 3) + (t << 1);
            const uint2 pl = *(const uint2*)&Ps[r0 * AST + kk];
            const uint2 ph = *(const uint2*)&Ps[(r0 + 8) * AST + kk];
#pragma unroll
            for (int nt = 0; nt < 8; nt++) {
                const uint32_t b0 = Vs[kk * VST + (nt << 3) + g];
                const uint32_t b1 = Vs[(kk + 1) * VST + (nt << 3) + g];
                mma_tf32(O[nt][0], O[nt][1], O[nt][2], O[nt][3],
                         pl.x, ph.x, pl.y, ph.y, b0, b1);
            }
        }
    }

    // epilogue: normalize, write d-permuted tf32 u32 (consumed by O-proj)
    const float inv0 = 1.f / l0;
    const float inv1 = 1.f / l1;
    uint32_t* dst0 = g_att + ((size_t)b * SEQ + q0) * DIMK + h * HD;
    uint32_t* dst1 = g_att + ((size_t)b * SEQ + q1) * DIMK + h * HD;
#pragma unroll
    for (int nt = 0; nt < 8; nt++) {
        const int nb = nt << 3;
        dst0[nb + pc0] = f32_tf32(O[nt][0] * inv0);
        dst0[nb + pc1] = f32_tf32(O[nt][1] * inv0);
        dst1[nb + pc0] = f32_tf32(O[nt][2] * inv1);
        dst1[nb + pc1] = f32_tf32(O[nt][3] * inv1);
    }
}

// ---------------------------------------------------------------------------
extern "C" void kernel_launch(void* const* d_in, const int* in_sizes, int n_in,
                              void* d_out, int out_size)
{
    const float* x  = (const float*)d_in[0];
    const float* Wq = (const float*)d_in[1];
    const float* bq = (const float*)d_in[2];
    const float* Wk = (const float*)d_in[3];
    const float* bk = (const float*)d_in[4];
    const float* Wv = (const float*)d_in[5];
    const float* bv = (const float*)d_in[6];
    const float* Wo = (const float*)d_in[7];
    const float* bo = (const float*)d_in[8];
    float* out = (float*)d_out;

    uint32_t *qp, *kp, *vp, *ap, *xp, *wp;
    cudaGetSymbolAddress((void**)&qp, g_q);
    cudaGetSymbolAddress((void**)&kp, g_k);
    cudaGetSymbolAddress((void**)&vp, g_v);
    cudaGetSymbolAddress((void**)&ap, g_att);
    cudaGetSymbolAddress((void**)&xp, g_x32);
    cudaGetSymbolAddress((void**)&wp, g_w32);
    uint32_t* w0 = wp;
    uint32_t* w1 = wp + (size_t)DIMK * DIMK;
    uint32_t* w2 = wp + 2 * (size_t)DIMK * DIMK;
    uint32_t* w3 = wp + 3 * (size_t)DIMK * DIMK;

    cudaFuncSetAttribute(gemm_mma,
                         cudaFuncAttributeMaxDynamicSharedMemorySize, SM_GEMM);
    cudaFuncSetAttribute(attn_mma,
                         cudaFuncAttributeMaxDynamicSharedMemorySize, SMEM_AMMA);

    // pre-convert (k-permuted) x and all weights (2 launches)
    const int nx4 = M_TOT * DIMK / 4;
    const int nw4 = DIMK * DIMK / 4;
    conv_x<<<(nx4 + 255) / 256, 256>>>(x, xp, nx4);
    dim3 gw(nw4 / 256, 4);
    conv_w<<<gw, 256>>>(Wq, Wk, Wv, Wo, wp);

    dim3 gqkv(DIMK / BN, M_TOT / BM, 3);   // fused Q/K/V projections
    gemm_mma<<<gqkv, 128, SM_GEMM>>>(xp, w0, w1, w2, bq, bk, bv,
                                     qp, kp, vp, nullptr, 1);
    attn_mma<<<BSZ * H * (SEQ / 64), 128, SMEM_AMMA>>>();
    dim3 go(DIMK / BN, M_TOT / BM, 1);     // output projection (fp32 out)
    gemm_mma<<<go, 128, SM_GEMM>>>(ap, w3, w3, w3, bo, bo, bo,
                                   nullptr, nullptr, nullptr, out, 0);
}

// round 14
// speedup vs baseline: 1.2890x; 1.0082x over previous
#include <cuda_runtime.h>
#include <cstdint>

#define DIMK 1024
#define BSZ  2
#define SEQ  4096
#define H    16
#define HD   64
#define M_TOT (BSZ * SEQ)   // 8192

// ---------------------------------------------------------------------------
// Scratch (allocation-free). tf32 bit patterns as u32. k-dimension buffers use
// perm8(k) = ((k&3)<<1)|((k&4)>>2) within each 8-group so mma fragment loads
// (cols t, t+4) become adjacent 64-bit loads.
// ---------------------------------------------------------------------------
__device__ uint32_t g_q[(size_t)BSZ * H * SEQ * HD];      // d-permuted
__device__ uint32_t g_k[(size_t)BSZ * H * SEQ * HD];      // d-permuted
__device__ uint32_t g_v[(size_t)BSZ * H * SEQ * HD];      // unpermuted
__device__ uint32_t g_att[(size_t)BSZ * SEQ * DIMK];      // d-permuted
__device__ uint32_t g_x32[(size_t)M_TOT * DIMK];          // k-permuted
__device__ uint32_t g_w32[4][(size_t)DIMK * DIMK];        // k-permuted

__device__ __forceinline__ int perm8(int k) { return ((k & 3) << 1) | ((k & 4) >> 2); }

__device__ __forceinline__ uint32_t f32_tf32(float f) {
    uint32_t r; asm("cvt.rna.tf32.f32 %0, %1;" : "=r"(r) : "f"(f)); return r;
}
__device__ __forceinline__ float ex2f(float x) {
    float r; asm("ex2.approx.f32 %0, %1;" : "=f"(r) : "f"(x)); return r;
}
__device__ __forceinline__ uint32_t smem_u32(const void* p) {
    uint32_t a;
    asm("{ .reg .u64 t; cvta.to.shared.u64 t, %1; cvt.u32.u64 %0, t; }" : "=r"(a) : "l"(p));
    return a;
}
__device__ __forceinline__ void cp16(uint32_t s, const void* g) {
    asm volatile("cp.async.cg.shared.global [%0], [%1], 16;" :: "r"(s), "l"(g));
}
#define CP_COMMIT()  asm volatile("cp.async.commit_group;" ::: "memory")
#define CP_WAIT(n)   asm volatile("cp.async.wait_group %0;" :: "n"(n) : "memory")

__device__ __forceinline__ void mma_tf32(float& c0, float& c1, float& c2, float& c3,
                                         uint32_t a0, uint32_t a1, uint32_t a2, uint32_t a3,
                                         uint32_t b0, uint32_t b1) {
    asm volatile("mma.sync.aligned.m16n8k8.row.col.f32.tf32.tf32.f32 "
        "{%0,%1,%2,%3}, {%4,%5,%6,%7}, {%8,%9}, {%0,%1,%2,%3};"
        : "+f"(c0), "+f"(c1), "+f"(c2), "+f"(c3)
        : "r"(a0), "r"(a1), "r"(a2), "r"(a3), "r"(b0), "r"(b1));
}

// ---------------------------------------------------------------------------
// fp32 -> tf32 with k-permutation. conv_x for activations; conv_w does all 4
// weight matrices in one launch.
// ---------------------------------------------------------------------------
__device__ __forceinline__ void conv4(const float* __restrict__ src,
                                      uint32_t* __restrict__ dst, int i) {
    float4 v = ((const float4*)src)[i];
    const int c    = i << 2;
    const int base = c & ~7;
    const int off  = (c & 4) ? 1 : 0;
    dst[base + off + 0] = f32_tf32(v.x);
    dst[base + off + 2] = f32_tf32(v.y);
    dst[base + off + 4] = f32_tf32(v.z);
    dst[base + off + 6] = f32_tf32(v.w);
}

__global__ void __launch_bounds__(256) conv_x(const float* __restrict__ src,
                                              uint32_t* __restrict__ dst, int n4)
{
    const int i = blockIdx.x * blockDim.x + threadIdx.x;
    if (i < n4) conv4(src, dst, i);
}

__global__ void __launch_bounds__(256) conv_w(const float* __restrict__ s0,
                                              const float* __restrict__ s1,
                                              const float* __restrict__ s2,
                                              const float* __restrict__ s3,
                                              uint32_t* __restrict__ dst)
{
    const int z = blockIdx.y;
    const float* src = (z == 0) ? s0 : (z == 1) ? s1 : (z == 2) ? s2 : s3;
    const int i = blockIdx.x * blockDim.x + threadIdx.x;
    conv4(src, dst + (size_t)z * DIMK * DIMK, i);
}

// ---------------------------------------------------------------------------
// tf32 mma.sync GEMM (R11 config): CTA 128x128, 256 thr, 8 warps (2M x 4N),
// warp tile 64x32. 2-stage cp.async, 64-bit fragment loads.
// layout 1: scatter tf32 u32 -> [B,H,S,hd] (z<2 d-permuted, z==2 plain);
// layout 0: fp32 row-major.
// ---------------------------------------------------------------------------
#define BM 128
#define BN 128
#define BK 32
#define KST 40                           // 8 mod 32: LDS.64 conflict-free
#define STGW ((BM + BN) * KST)           // 10240 words / stage
#define SM_GEMM (2 * STGW * 4)           // 81920 B -> 2 CTAs/SM

__global__ void __launch_bounds__(256, 2) gemm_mma(const uint32_t* __restrict__ A,
                                                   const uint32_t* __restrict__ W0,
                                                   const uint32_t* __restrict__ W1,
                                                   const uint32_t* __restrict__ W2,
                                                   const float* __restrict__ b0p,
                                                   const float* __restrict__ b1p,
                                                   const float* __restrict__ b2p,
                                                   uint32_t* __restrict__ C0,
                                                   uint32_t* __restrict__ C1,
                                                   uint32_t* __restrict__ C2,
                                                   float* __restrict__ Cf,
                                                   int layout)
{
    extern __shared__ __align__(16) uint32_t gsm[];

    const int z = blockIdx.z;
    const uint32_t* W    = (z == 0) ? W0 : (z == 1) ? W1 : W2;
    const float*    bias = (z == 0) ? b0p : (z == 1) ? b1p : b2p;
    uint32_t*       C    = (z == 0) ? C0 : (z == 1) ? C1 : C2;

    const int tid  = threadIdx.x;
    const int wid  = tid >> 5;
    const int lane = tid & 31;
    const int g    = lane >> 2;
    const int t    = lane & 3;
    const int wm   = wid & 1;
    const int wn   = wid >> 1;
    const int m0   = blockIdx.y * BM;
    const int n0   = blockIdx.x * BN;

    const int lrow = tid >> 3;        // 0..31
    const int lc4  = (tid & 7) << 2;  // 0..28 step 4

    const uint32_t smb = smem_u32(gsm);

    float acc[4][4][4];
#pragma unroll
    for (int i = 0; i < 4; i++)
#pragma unroll
        for (int j = 0; j < 4; j++)
#pragma unroll
            for (int r = 0; r < 4; r++) acc[i][j][r] = 0.f;

    const int warpAm = wm * 64;
    const int warpBn = wn * 32;

    const uint32_t* Abase = A + (size_t)(m0 + lrow) * DIMK + lc4;
    const uint32_t* Wbase = W + (size_t)(n0 + lrow) * DIMK + lc4;
    const uint32_t sAoff  = smb + (uint32_t)(lrow * KST + lc4) * 4;
    const uint32_t sBoff  = sAoff + (uint32_t)(BM * KST) * 4;

    // prologue: chunk 0 into stage 0
#pragma unroll
    for (int it = 0; it < 4; it++) {
        const int ro = it << 5;
        cp16(sAoff + (uint32_t)(ro * KST) * 4, Abase + (size_t)ro * DIMK);
        cp16(sBoff + (uint32_t)(ro * KST) * 4, Wbase + (size_t)ro * DIMK);
    }
    CP_COMMIT();

    for (int c = 0; c < 32; c++) {
        CP_WAIT(0);          // chunk c resident
        __syncthreads();     // all warps done reading chunk c-1's stage

        if (c < 31) {
            const uint32_t sb = ((c + 1) & 1) * (uint32_t)(STGW * 4);
            const int k0 = (c + 1) * BK;
#pragma unroll
            for (int it = 0; it < 4; it++) {
                const int ro = it << 5;
                cp16(sAoff + sb + (uint32_t)(ro * KST) * 4, Abase + (size_t)ro * DIMK + k0);
                cp16(sBoff + sb + (uint32_t)(ro * KST) * 4, Wbase + (size_t)ro * DIMK + k0);
            }
            CP_COMMIT();     // overlaps this chunk's MMA
        }

        const uint32_t* As = gsm + (c & 1) * STGW;
        const uint32_t* Bs = As + BM * KST;

#pragma unroll
        for (int ks = 0; ks < 4; ks++) {
            const int kk = (ks << 3) + (t << 1);   // permuted cols t,t+4 adjacent
            uint2 al[4], ah[4], bb[4];
#pragma unroll
            for (int mt = 0; mt < 4; mt++) {
                const int rb = warpAm + (mt << 4);
                al[mt] = *(const uint2*)&As[(rb + g    ) * KST + kk];
                ah[mt] = *(const uint2*)&As[(rb + g + 8) * KST + kk];
            }
#pragma unroll
            for (int nt = 0; nt < 4; nt++) {
                const int nb = warpBn + (nt << 3);
                bb[nt] = *(const uint2*)&Bs[(nb + g) * KST + kk];
            }
#pragma unroll
            for (int mt = 0; mt < 4; mt++)
#pragma unroll
                for (int nt = 0; nt < 4; nt++)
                    mma_tf32(acc[mt][nt][0], acc[mt][nt][1],
                             acc[mt][nt][2], acc[mt][nt][3],
                             al[mt].x, ah[mt].x, al[mt].y, ah[mt].y,
                             bb[nt].x, bb[nt].y);
        }
    }

#pragma unroll
    for (int nt = 0; nt < 4; nt++) {
        const int n = n0 + warpBn + (nt << 3) + (t << 1);
        const float bx = bias[n], by = bias[n + 1];
#pragma unroll
        for (int mt = 0; mt < 4; mt++) {
            const int r0 = m0 + warpAm + (mt << 4) + g;
            const int r1 = r0 + 8;
            const float v00 = acc[mt][nt][0] + bx, v01 = acc[mt][nt][1] + by;
            const float v10 = acc[mt][nt][2] + bx, v11 = acc[mt][nt][3] + by;
            if (layout == 0) {
                *(float2*)(Cf + (size_t)r0 * DIMK + n) = make_float2(v00, v01);
                *(float2*)(Cf + (size_t)r1 * DIMK + n) = make_float2(v10, v11);
            } else {
                const int h_ = n >> 6, d_ = n & 63;
                const int b0_ = r0 >> 12, s0_ = r0 & 4095;
                const int b1_ = r1 >> 12, s1_ = r1 & 4095;
                uint32_t* p0 = C + (((size_t)(b0_ * H + h_)) * SEQ + s0_) * HD;
                uint32_t* p1 = C + (((size_t)(b1_ * H + h_)) * SEQ + s1_) * HD;
                if (z < 2) {   // Q,K: d-permuted
                    const int pc0 = (d_ & ~7) | perm8(d_ & 7);
                    const int pc1 = (d_ & ~7) | perm8((d_ & 7) + 1);
                    p0[pc0] = f32_tf32(v00); p0[pc1] = f32_tf32(v01);
                    p1[pc0] = f32_tf32(v10); p1[pc1] = f32_tf32(v11);
                } else {       // V: unpermuted
                    *(uint2*)(p0 + d_) = make_uint2(f32_tf32(v00), f32_tf32(v01));
                    *(uint2*)(p1 + d_) = make_uint2(f32_tf32(v10), f32_tf32(v11));
                }
            }
        }
    }
}

// ---------------------------------------------------------------------------
// Tensorized sliding-window attention. Q fragments hoisted to registers;
// Ps aliases dead Qs buffer (2 barriers/tile). Mask applied ONLY on the two
// boundary tiles (kt==qi diagonal, kt==qi-8 leftmost): for all inner tiles
// q-c is provably in [1,511], so the mask is identity there.
// ---------------------------------------------------------------------------
#define AST 72
#define VST 68
#define SMEM_AMMA ((2 * 64 * AST + 64 * VST) * 4)   // 54272 B -> 4 CTAs/SM

__global__ void __launch_bounds__(128, 4) attn_mma()
{
    extern __shared__ __align__(16) uint32_t smu[];
    uint32_t* Qs = smu;                  // [64][AST] ; dead after prologue -> Ps
    uint32_t* Ks = smu + 64 * AST;       // [64][AST]
    uint32_t* Vs = smu + 2 * 64 * AST;   // [64][VST] row-permuted

    const int tid  = threadIdx.x;
    const int w    = tid >> 5;
    const int lane = tid & 31;
    const int g    = lane >> 2;
    const int t    = lane & 3;

    const int qi = blockIdx.x & 63;
    const int h  = (blockIdx.x >> 6) & 15;
    const int b  = blockIdx.x >> 10;
    const int p0 = qi << 6;

    const size_t headoff = ((size_t)(b * H + h)) * SEQ * HD;
    const uint32_t* qbase = g_q + headoff;
    const uint32_t* kbase = g_k + headoff;
    const uint32_t* vbase = g_v + headoff;

    const uint32_t smb = smem_u32(smu);
    const uint32_t Ksb = smb + (uint32_t)(64 * AST) * 4;
    const uint32_t Vsb = smb + (uint32_t)(2 * 64 * AST) * 4;

    // stage Q, then hoist this warp's fragments into registers
#pragma unroll
    for (int it = 0; it < 8; it++) {
        const int u = tid + (it << 7);
        const int row = u >> 4, c4 = (u & 15) << 2;
        cp16(smb + (uint32_t)(row * AST + c4) * 4, qbase + (size_t)(p0 + row) * HD + c4);
    }
    CP_COMMIT(); CP_WAIT(0);
    __syncthreads();

    const int r0 = (w << 4) + g;
    const int q0 = p0 + r0;
    const int q1 = q0 + 8;
    const int pc0 = perm8(t << 1);
    const int pc1 = perm8((t << 1) + 1);

    uint2 qfl[8], qfh[8];
#pragma unroll
    for (int ks = 0; ks < 8; ks++) {
        const int kk = (ks << 3) + (t << 1);
        qfl[ks] = *(const uint2*)&Qs[r0 * AST + kk];
        qfh[ks] = *(const uint2*)&Qs[(r0 + 8) * AST + kk];
    }
    __syncthreads();   // Qs now dead -> becomes Ps
    uint32_t* Ps = Qs;

    float O[8][4];
#pragma unroll
    for (int nt = 0; nt < 8; nt++)
#pragma unroll
        for (int r = 0; r < 4; r++) O[nt][r] = 0.f;
    float m0 = -1.0e4f, m1 = -1.0e4f, l0 = 0.f, l1 = 0.f;

    const float SC = 0.125f * 1.44269504f;   // hd^-0.5 * log2(e)

    const int ktlo = (qi >= 8) ? (qi - 8) : 0;
    for (int kt = ktlo; kt <= qi; kt++) {
        const int t0 = kt << 6;
        const bool boundary = (kt == qi) || (kt == qi - 8);

        __syncthreads();   // prior QK reads of Ks + PV reads of Vs complete
#pragma unroll
        for (int it = 0; it < 8; it++) {
            const int u = tid + (it << 7);
            const int row = u >> 4, c4 = (u & 15) << 2;
            const int pr = (row & ~7) | perm8(row & 7);   // V row permutation
            cp16(Ksb + (uint32_t)(row * AST + c4) * 4, kbase + (size_t)(t0 + row) * HD + c4);
            cp16(Vsb + (uint32_t)(pr  * VST + c4) * 4, vbase + (size_t)(t0 + row) * HD + c4);
        }
        CP_COMMIT(); CP_WAIT(0);
        __syncthreads();

        // S = Q K^T  (Q from registers)
        float s[8][4];
#pragma unroll
        for (int nt = 0; nt < 8; nt++)
#pragma unroll
            for (int r = 0; r < 4; r++) s[nt][r] = 0.f;

#pragma unroll
        for (int ks = 0; ks < 8; ks++) {
            const int kk = (ks << 3) + (t << 1);
#pragma unroll
            for (int nt = 0; nt < 8; nt++) {
                const uint2 kb = *(const uint2*)&Ks[((nt << 3) + g) * AST + kk];
                mma_tf32(s[nt][0], s[nt][1], s[nt][2], s[nt][3],
                         qfl[ks].x, qfh[ks].x, qfl[ks].y, qfh[ks].y, kb.x, kb.y);
            }
        }

        // scale (+ mask only on boundary tiles) + online softmax
        float rmax0 = -3.0e4f, rmax1 = -3.0e4f;
        if (boundary) {
#pragma unroll
            for (int nt = 0; nt < 8; nt++) {
                const int c = t0 + (nt << 3) + (t << 1);
                s[nt][0] = ((unsigned)(q0 - c)     < 512u) ? s[nt][0] * SC : -3.0e4f;
                s[nt][1] = ((unsigned)(q0 - c - 1) < 512u) ? s[nt][1] * SC : -3.0e4f;
                s[nt][2] = ((unsigned)(q1 - c)     < 512u) ? s[nt][2] * SC : -3.0e4f;
                s[nt][3] = ((unsigned)(q1 - c - 1) < 512u) ? s[nt][3] * SC : -3.0e4f;
                rmax0 = fmaxf(rmax0, fmaxf(s[nt][0], s[nt][1]));
                rmax1 = fmaxf(rmax1, fmaxf(s[nt][2], s[nt][3]));
            }
        } else {
#pragma unroll
            for (int nt = 0; nt < 8; nt++) {
                s[nt][0] *= SC; s[nt][1] *= SC;
                s[nt][2] *= SC; s[nt][3] *= SC;
                rmax0 = fmaxf(rmax0, fmaxf(s[nt][0], s[nt][1]));
                rmax1 = fmaxf(rmax1, fmaxf(s[nt][2], s[nt][3]));
            }
        }
        rmax0 = fmaxf(rmax0, __shfl_xor_sync(0xffffffffu, rmax0, 1));
        rmax0 = fmaxf(rmax0, __shfl_xor_sync(0xffffffffu, rmax0, 2));
        rmax1 = fmaxf(rmax1, __shfl_xor_sync(0xffffffffu, rmax1, 1));
        rmax1 = fmaxf(rmax1, __shfl_xor_sync(0xffffffffu, rmax1, 2));

        const float mn0 = fmaxf(m0, rmax0);
        const float mn1 = fmaxf(m1, rmax1);
        const float al0 = ex2f(m0 - mn0);
        const float al1 = ex2f(m1 - mn1);
        m0 = mn0; m1 = mn1;

        float rs0 = 0.f, rs1 = 0.f;
#pragma unroll
        for (int nt = 0; nt < 8; nt++) {
            const float p00 = ex2f(s[nt][0] - mn0);
            const float p01 = ex2f(s[nt][1] - mn0);
            const float p10 = ex2f(s[nt][2] - mn1);
            const float p11 = ex2f(s[nt][3] - mn1);
            rs0 += p00 + p01;
            rs1 += p10 + p11;
            const int nb = nt << 3;
            Ps[r0 * AST + nb + pc0]       = f32_tf32(p00);
            Ps[r0 * AST + nb + pc1]       = f32_tf32(p01);
            Ps[(r0 + 8) * AST + nb + pc0] = f32_tf32(p10);
            Ps[(r0 + 8) * AST + nb + pc1] = f32_tf32(p11);
        }
        rs0 += __shfl_xor_sync(0xffffffffu, rs0, 1);
        rs0 += __shfl_xor_sync(0xffffffffu, rs0, 2);
        rs1 += __shfl_xor_sync(0xffffffffu, rs1, 1);
        rs1 += __shfl_xor_sync(0xffffffffu, rs1, 2);

        l0 = l0 * al0 + rs0;
        l1 = l1 * al1 + rs1;
#pragma unroll
        for (int nt = 0; nt < 8; nt++) {
            O[nt][0] *= al0; O[nt][1] *= al0;
            O[nt][2] *= al1; O[nt][3] *= al1;
        }
        __syncwarp();      // Ps rows are warp-private

        // O += P V
#pragma unroll
        for (int ks = 0; ks < 8; ks++) {
            const int kk = (ks << 3) + (t << 1);
            const uint2 pl = *(const uint2*)&Ps[r0 * AST + kk];
            const uint2 ph = *(const uint2*)&Ps[(r0 + 8) * AST + kk];
#pragma unroll
            for (int nt = 0; nt < 8; nt++) {
                const uint32_t b0 = Vs[kk * VST + (nt << 3) + g];
                const uint32_t b1 = Vs[(kk + 1) * VST + (nt << 3) + g];
                mma_tf32(O[nt][0], O[nt][1], O[nt][2], O[nt][3],
                         pl.x, ph.x, pl.y, ph.y, b0, b1);
            }
        }
    }

    // epilogue: normalize, write d-permuted tf32 u32 (consumed by O-proj)
    const float inv0 = 1.f / l0;
    const float inv1 = 1.f / l1;
    uint32_t* dst0 = g_att + ((size_t)b * SEQ + q0) * DIMK + h * HD;
    uint32_t* dst1 = g_att + ((size_t)b * SEQ + q1) * DIMK + h * HD;
#pragma unroll
    for (int nt = 0; nt < 8; nt++) {
        const int nb = nt << 3;
        dst0[nb + pc0] = f32_tf32(O[nt][0] * inv0);
        dst0[nb + pc1] = f32_tf32(O[nt][1] * inv0);
        dst1[nb + pc0] = f32_tf32(O[nt][2] * inv1);
        dst1[nb + pc1] = f32_tf32(O[nt][3] * inv1);
    }
}

// ---------------------------------------------------------------------------
extern "C" void kernel_launch(void* const* d_in, const int* in_sizes, int n_in,
                              void* d_out, int out_size)
{
    const float* x  = (const float*)d_in[0];
    const float* Wq = (const float*)d_in[1];
    const float* bq = (const float*)d_in[2];
    const float* Wk = (const float*)d_in[3];
    const float* bk = (const float*)d_in[4];
    const float* Wv = (const float*)d_in[5];
    const float* bv = (const float*)d_in[6];
    const float* Wo = (const float*)d_in[7];
    const float* bo = (const float*)d_in[8];
    float* out = (float*)d_out;

    uint32_t *qp, *kp, *vp, *ap, *xp, *wp;
    cudaGetSymbolAddress((void**)&qp, g_q);
    cudaGetSymbolAddress((void**)&kp, g_k);
    cudaGetSymbolAddress((void**)&vp, g_v);
    cudaGetSymbolAddress((void**)&ap, g_att);
    cudaGetSymbolAddress((void**)&xp, g_x32);
    cudaGetSymbolAddress((void**)&wp, g_w32);
    uint32_t* w0 = wp;
    uint32_t* w1 = wp + (size_t)DIMK * DIMK;
    uint32_t* w2 = wp + 2 * (size_t)DIMK * DIMK;
    uint32_t* w3 = wp + 3 * (size_t)DIMK * DIMK;

    cudaFuncSetAttribute(gemm_mma,
                         cudaFuncAttributeMaxDynamicSharedMemorySize, SM_GEMM);
    cudaFuncSetAttribute(attn_mma,
                         cudaFuncAttributeMaxDynamicSharedMemorySize, SMEM_AMMA);

    // pre-convert (k-permuted) x and all weights
    const int nx4 = M_TOT * DIMK / 4;
    const int nw4 = DIMK * DIMK / 4;
    conv_x<<<(nx4 + 255) / 256, 256>>>(x, xp, nx4);
    dim3 gw(nw4 / 256, 4);
    conv_w<<<gw, 256>>>(Wq, Wk, Wv, Wo, wp);

    dim3 gqkv(DIMK / BN, M_TOT / BM, 3);   // fused Q/K/V projections
    gemm_mma<<<gqkv, 256, SM_GEMM>>>(xp, w0, w1, w2, bq, bk, bv,
                                     qp, kp, vp, nullptr, 1);
    attn_mma<<<BSZ * H * (SEQ / 64), 128, SMEM_AMMA>>>();
    dim3 go(DIMK / BN, M_TOT / BM, 1);     // output projection (fp32 out)
    gemm_mma<<<go, 256, SM_GEMM>>>(ap, w3, w3, w3, bo, bo, bo,
                                   nullptr, nullptr, nullptr, out, 0);
}